// round 13
// baseline (speedup 1.0000x reference)
#include <cuda_runtime.h>
#include <cuda_bf16.h>
#include <cstdint>

#define BRANCHES 4
#define NB 16
#define CPB 64
#define HGT 80
#define WID 80
#define NPIX 6400
#define NHEADS 8
#define NTILES 100

// ---------------- scratch ----------------------------------------------------
__device__ float    g_y    [(size_t)BRANCHES*NB*CPB*NPIX];
__device__ float    g_q    [(size_t)BRANCHES*NB*CPB*NPIX];    // raw q
__device__ float    g_ctx  [(size_t)BRANCHES*NB*NHEADS*64];   // zeroed by prep, atomic acc
__device__ float    g_cpart[(size_t)NTILES*64*512];
__device__ float    g_pm   [(size_t)4096*NTILES];
__device__ float    g_ps   [(size_t)4096*NTILES];
__device__ float    g_qm   [(size_t)4096];
__device__ float    g_qs   [(size_t)4096];
__device__ float    g_att  [(size_t)BRANCHES*NB*CPB*NPIX];    // tf32-rounded
__device__ uint32_t g_wf32 [65536];                            // wf as tf32 bits
__device__ uint32_t g_wp32 [4096];                             // wproj as tf32 bits
__device__ uint32_t g_wq_hi[192*32];                           // wqkv bf16-hi pairs
__device__ uint32_t g_wq_lo[192*32];                           // wqkv bf16-lo pairs

// ---------------- helpers ------------------------------------------------------
__device__ __forceinline__ uint32_t f2tf32(float x) {
    uint32_t r;
    asm("cvt.rna.tf32.f32 %0, %1;" : "=r"(r) : "f"(x));
    return r;
}
__device__ __forceinline__ void mma_tf32(float d[4],
                                         uint32_t a0, uint32_t a1, uint32_t a2, uint32_t a3,
                                         uint32_t b0, uint32_t b1) {
    asm volatile(
        "mma.sync.aligned.m16n8k8.row.col.f32.tf32.tf32.f32 "
        "{%0,%1,%2,%3}, {%4,%5,%6,%7}, {%8,%9}, {%0,%1,%2,%3};"
        : "+f"(d[0]), "+f"(d[1]), "+f"(d[2]), "+f"(d[3])
        : "r"(a0), "r"(a1), "r"(a2), "r"(a3), "r"(b0), "r"(b1));
}
__device__ __forceinline__ void mma_bf16(float d[4],
                                         uint32_t a0, uint32_t a1, uint32_t a2, uint32_t a3,
                                         uint32_t b0, uint32_t b1) {
    asm volatile(
        "mma.sync.aligned.m16n8k16.row.col.f32.bf16.bf16.f32 "
        "{%0,%1,%2,%3}, {%4,%5,%6,%7}, {%8,%9}, {%0,%1,%2,%3};"
        : "+f"(d[0]), "+f"(d[1]), "+f"(d[2]), "+f"(d[3])
        : "r"(a0), "r"(a1), "r"(a2), "r"(a3), "r"(b0), "r"(b1));
}
__device__ __forceinline__ void bf16_split_pair(float f0, float f1,
                                                uint32_t& hi, uint32_t& lo) {
    __nv_bfloat162 hp = __floats2bfloat162_rn(f0, f1);
    float g0 = __bfloat162float(hp.x);
    float g1 = __bfloat162float(hp.y);
    __nv_bfloat162 lp = __floats2bfloat162_rn(f0 - g0, f1 - g1);
    hi = *reinterpret_cast<uint32_t*>(&hp);
    lo = *reinterpret_cast<uint32_t*>(&lp);
}

// ---------------- K0: prep ----------------------------------------------------
__global__ void prep_kernel(const float* __restrict__ wf,
                            const float* __restrict__ wproj,
                            const float* __restrict__ wqkv) {
    int i = blockIdx.x * 1024 + threadIdx.x;
    g_wf32[i] = f2tf32(wf[i]);
    if (i < 32768) g_ctx[i] = 0.f;
    if (i < 4096)  g_wp32[i] = f2tf32(wproj[i]);
    if (i < 6144) {
        int j = i >> 5, cp = i & 31;
        float w0 = wqkv[j*64 + 2*cp];
        float w1 = wqkv[j*64 + 2*cp + 1];
        uint32_t hi, lo;
        bf16_split_pair(w0, w1, hi, lo);
        g_wq_hi[i] = hi;
        g_wq_lo[i] = lo;
    }
}

// ---------------- K1: fused depthwise conv -------------------------------------
template<int KS>
__device__ __forceinline__ void dwconv_body(const float* __restrict__ x,
                                            const float* __restrict__ w,
                                            const float* __restrict__ bias,
                                            int br, int c, float* tile, float* wsm)
{
    const int b    = blockIdx.z;
    const int row0 = blockIdx.x * 16;
    const int tid  = threadIdx.x;

    if (tid < KS*KS) wsm[tid] = w[c*KS*KS + tid];
    const float bv = bias[c];
    const float* xp = x + ((size_t)b*256 + (size_t)br*64 + c) * NPIX;

    for (int idx = tid; idx < 24*88; idx += 320) {
        int r  = idx / 88, cl = idx % 88;
        int gh = row0 - 4 + r, gw = cl - 4;
        float v = 0.f;
        if (gh >= 0 && gh < HGT && gw >= 0 && gw < WID) v = xp[gh*WID + gw];
        tile[idx] = v;
    }
    __syncthreads();

    const int tx = tid % 20, ty = tid / 20;
    const int col0 = tx * 4;
    constexpr int PAD = KS / 2;
    constexpr int OFF = 4 - PAD;
    float a0 = 0.f, a1 = 0.f, a2 = 0.f, a3 = 0.f;
    float win[12];
    #pragma unroll
    for (int kh = 0; kh < KS; kh++) {
        int rb = (ty + 4 - PAD + kh)*88 + col0;
        float4 w0 = *(const float4*)&tile[rb];
        float4 w1 = *(const float4*)&tile[rb + 4];
        float4 w2 = *(const float4*)&tile[rb + 8];
        win[0]=w0.x; win[1]=w0.y; win[2]=w0.z;  win[3]=w0.w;
        win[4]=w1.x; win[5]=w1.y; win[6]=w1.z;  win[7]=w1.w;
        win[8]=w2.x; win[9]=w2.y; win[10]=w2.z; win[11]=w2.w;
        #pragma unroll
        for (int kw = 0; kw < KS; kw++) {
            float wv = wsm[kh*KS + kw];
            a0 += win[OFF + kw    ] * wv;
            a1 += win[OFF + kw + 1] * wv;
            a2 += win[OFF + kw + 2] * wv;
            a3 += win[OFF + kw + 3] * wv;
        }
    }
    int cb = (ty + 4)*88 + col0 + 4;
    float4 res = *(const float4*)&tile[cb];
    float* yp = g_y + (((size_t)br*NB + b)*CPB + c)*NPIX + (row0 + ty)*WID + col0;
    float4 r;
    r.x = fmaxf(a0 + bv + res.x, 0.f);
    r.y = fmaxf(a1 + bv + res.y, 0.f);
    r.z = fmaxf(a2 + bv + res.z, 0.f);
    r.w = fmaxf(a3 + bv + res.w, 0.f);
    *(float4*)yp = r;
}

__global__ void dwconv_all_kernel(const float* __restrict__ x,
                                  const float* __restrict__ w3, const float* __restrict__ b3,
                                  const float* __restrict__ w5, const float* __restrict__ b5,
                                  const float* __restrict__ w7, const float* __restrict__ b7,
                                  const float* __restrict__ w9, const float* __restrict__ b9)
{
    __shared__ float tile[24*88];
    __shared__ float wsm[81];
    const int br = blockIdx.y >> 6;
    const int c  = blockIdx.y & 63;
    switch (br) {
        case 0: dwconv_body<3>(x, w3, b3, 0, c, tile, wsm); break;
        case 1: dwconv_body<5>(x, w5, b5, 1, c, tile, wsm); break;
        case 2: dwconv_body<7>(x, w7, b7, 2, c, tile, wsm); break;
        default: dwconv_body<9>(x, w9, b9, 3, c, tile, wsm); break;
    }
}

// ---------------- K2: qkv bf16 3-term MMA + softmax/ctx/stats+scatter ----------
#define QSTR 194
#define WQSU 36
#define YSS  72
__global__ void qkv_kernel()
{
    extern __shared__ uint32_t smu[];
    uint32_t* wqh = smu;
    uint32_t* wql = smu + 192*WQSU;
    float*    ys  = (float*)(smu + 13824);
    const int tid  = threadIdx.x;
    const int brb  = blockIdx.y;
    const int tile = blockIdx.x;
    const int n0   = tile * 64;

    const float* yp = g_y + (size_t)brb * CPB * NPIX;
    for (int idx = tid; idx < 1536; idx += 256) {
        int j = idx >> 3, w4 = (idx & 7) * 4;
        uint4 vh = *(const uint4*)&g_wq_hi[j*32 + w4];
        uint4 vl = *(const uint4*)&g_wq_lo[j*32 + w4];
        *(uint4*)&wqh[j*WQSU + w4] = vh;
        *(uint4*)&wql[j*WQSU + w4] = vl;
    }
    for (int idx = tid; idx < 1024; idx += 256) {
        int c = idx >> 4, t4 = (idx & 15) * 4;
        float4 v = *(const float4*)&yp[(size_t)c*NPIX + n0 + t4];
        *(float4*)&ys[c*YSS + t4] = v;
    }
    __syncthreads();

    const int warp = tid >> 5, lane = tid & 31;
    const int wm = (warp >> 2) * 96;
    const int wn = (warp & 3) * 16;
    const int g = lane >> 2, t = lane & 3;

    float d[6][2][4];
    #pragma unroll
    for (int mf = 0; mf < 6; mf++)
        #pragma unroll
        for (int nf = 0; nf < 2; nf++)
            #pragma unroll
            for (int r = 0; r < 4; r++) d[mf][nf][r] = 0.f;

    #pragma unroll
    for (int ks = 0; ks < 4; ks++) {
        const int k0 = ks * 16;
        const int ci = ks * 8 + t;
        uint32_t bh[2][2], bl[2][2];
        #pragma unroll
        for (int nf = 0; nf < 2; nf++) {
            int ncol = wn + nf*8 + g;
            float f0 = ys[(k0 + 2*t    )*YSS + ncol];
            float f1 = ys[(k0 + 2*t + 1)*YSS + ncol];
            float f2 = ys[(k0 + 2*t + 8)*YSS + ncol];
            float f3 = ys[(k0 + 2*t + 9)*YSS + ncol];
            bf16_split_pair(f0, f1, bh[nf][0], bl[nf][0]);
            bf16_split_pair(f2, f3, bh[nf][1], bl[nf][1]);
        }
        #pragma unroll
        for (int mf = 0; mf < 6; mf++) {
            int r0 = wm + mf*16 + g;
            uint32_t ah0 = wqh[(r0    )*WQSU + ci];
            uint32_t ah1 = wqh[(r0 + 8)*WQSU + ci];
            uint32_t ah2 = wqh[(r0    )*WQSU + ci + 4];
            uint32_t ah3 = wqh[(r0 + 8)*WQSU + ci + 4];
            uint32_t al0 = wql[(r0    )*WQSU + ci];
            uint32_t al1 = wql[(r0 + 8)*WQSU + ci];
            uint32_t al2 = wql[(r0    )*WQSU + ci + 4];
            uint32_t al3 = wql[(r0 + 8)*WQSU + ci + 4];
            #pragma unroll
            for (int nf = 0; nf < 2; nf++) {
                mma_bf16(d[mf][nf], ah0, ah1, ah2, ah3, bl[nf][0], bl[nf][1]);
                mma_bf16(d[mf][nf], al0, al1, al2, al3, bh[nf][0], bh[nf][1]);
                mma_bf16(d[mf][nf], ah0, ah1, ah2, ah3, bh[nf][0], bh[nf][1]);
            }
        }
    }
    __syncthreads();

    float* qkvs = (float*)smu;  // [t=64][j stride QSTR]
    #pragma unroll
    for (int mf = 0; mf < 6; mf++) {
        int r0 = wm + mf*16 + g;
        #pragma unroll
        for (int nf = 0; nf < 2; nf++) {
            int c0 = wn + nf*8 + 2*t;
            qkvs[(c0    )*QSTR + r0    ] = d[mf][nf][0];
            qkvs[(c0 + 1)*QSTR + r0    ] = d[mf][nf][1];
            qkvs[(c0    )*QSTR + r0 + 8] = d[mf][nf][2];
            qkvs[(c0 + 1)*QSTR + r0 + 8] = d[mf][nf][3];
        }
    }
    __syncthreads();

    // k softmax over head-dim (8)
    for (int th = tid; th < 512; th += 256) {
        int tt = th & 63, h = th >> 6;
        float* kr = &qkvs[tt*QSTR + 64 + h*8];
        float kv[8];
        #pragma unroll
        for (int dd = 0; dd < 8; dd++) kv[dd] = kr[dd];
        float m = kv[0];
        #pragma unroll
        for (int dd = 1; dd < 8; dd++) m = fmaxf(m, kv[dd]);
        float e[8]; float s = 0.f;
        #pragma unroll
        for (int dd = 0; dd < 8; dd++) { e[dd] = __expf(kv[dd] - m); s += e[dd]; }
        float inv = 1.f / s;
        #pragma unroll
        for (int dd = 0; dd < 8; dd++) kr[dd] = e[dd] * inv;
    }
    __syncthreads();

    // per-tile q stats + fused RAW q scatter (values already in registers)
    {
        int hd = tid >> 2, part = tid & 3;
        float vals[16];
        #pragma unroll
        for (int i = 0; i < 16; i++) vals[i] = qkvs[(part*16 + i)*QSTR + hd];
        float m = vals[0];
        #pragma unroll
        for (int i = 1; i < 16; i++) m = fmaxf(m, vals[i]);
        m = fmaxf(m, __shfl_xor_sync(0xffffffffu, m, 1));
        m = fmaxf(m, __shfl_xor_sync(0xffffffffu, m, 2));
        float s = 0.f;
        #pragma unroll
        for (int i = 0; i < 16; i++) s += __expf(vals[i] - m);
        s += __shfl_xor_sync(0xffffffffu, s, 1);
        s += __shfl_xor_sync(0xffffffffu, s, 2);
        size_t r = (size_t)brb*64 + hd;
        if (part == 0) {
            g_pm[r*NTILES + tile] = m;
            g_ps[r*NTILES + tile] = s;
        }
        float* qg = &g_q[r*NPIX + n0 + part*16];
        *(float4*)&qg[0]  = make_float4(vals[0],  vals[1],  vals[2],  vals[3]);
        *(float4*)&qg[4]  = make_float4(vals[4],  vals[5],  vals[6],  vals[7]);
        *(float4*)&qg[8]  = make_float4(vals[8],  vals[9],  vals[10], vals[11]);
        *(float4*)&qg[12] = make_float4(vals[12], vals[13], vals[14], vals[15]);
    }

    // partial ctx
    {
        int h  = tid >> 5;
        int dd = (tid >> 2) & 7;
        int ep = tid & 3;
        float ce0 = 0.f, ce1 = 0.f;
        #pragma unroll 4
        for (int tt = 0; tt < 64; tt++) {
            float  kv = qkvs[tt*QSTR + 64 + h*8 + dd];
            float2 vv = *(const float2*)&qkvs[tt*QSTR + 128 + h*8 + 2*ep];
            ce0 += kv * vv.x;
            ce1 += kv * vv.y;
        }
        float2 r = make_float2(ce0, ce1);
        *(float2*)&g_cpart[((size_t)tile*64 + brb)*512 + h*64 + dd*8 + 2*ep] = r;
    }
}

// ---------------- K3a: reduce partial ctx (25-way over tiles) -----------------
__global__ void ctx_reduce_kernel()
{
    const int brb = blockIdx.x;
    const int t0  = blockIdx.y * 4;
    const int tid = threadIdx.x;
    float s = 0.f;
    const float* p = g_cpart + (size_t)brb*512 + tid;
    #pragma unroll
    for (int t = 0; t < 4; t++)
        s += p[(size_t)(t0 + t)*64*512];
    atomicAdd(&g_ctx[(size_t)brb*512 + tid], s);
}

// ---------------- K3b: combine per-tile q stats (warp per row) ----------------
__global__ void qcombine_kernel()
{
    const int lane = threadIdx.x & 31;
    const int r    = blockIdx.x * 8 + (threadIdx.x >> 5);
    const float* pm = g_pm + (size_t)r*NTILES;
    const float* ps = g_ps + (size_t)r*NTILES;

    float mv[4]; float m = -1e30f;
    #pragma unroll
    for (int j = 0; j < 4; j++) {
        int t = lane + 32*j;
        mv[j] = (t < NTILES) ? pm[t] : -1e30f;
        m = fmaxf(m, mv[j]);
    }
    #pragma unroll
    for (int off = 16; off; off >>= 1)
        m = fmaxf(m, __shfl_xor_sync(0xffffffffu, m, off));

    float s = 0.f;
    #pragma unroll
    for (int j = 0; j < 4; j++) {
        int t = lane + 32*j;
        if (t < NTILES) s += ps[t] * __expf(mv[j] - m);
    }
    #pragma unroll
    for (int off = 16; off; off >>= 1)
        s += __shfl_xor_sync(0xffffffffu, s, off);

    if (lane == 0) { g_qm[r] = m; g_qs[r] = s; }
}

// ---------------- K5: softmax(q)@ctx, reshape, proj (tf32 MMA), scale (R11) ---
#define WPS 72
#define OSS 68
__global__ void attn_out_kernel(const float* __restrict__ bproj,
                                const float* __restrict__ scale)
{
    __shared__ uint32_t wp [64*WPS];
    __shared__ float out_s[32*OSS];
    __shared__ float p_s  [32*OSS];
    __shared__ float ctx_s[64];
    __shared__ float m_s[8];
    const int tid = threadIdx.x;
    const int brb = blockIdx.y;
    const int br  = brb >> 4;

    for (int idx = tid; idx < 4096; idx += 256) {
        int o = idx >> 6, f = idx & 63;
        wp[f*WPS + o] = g_wp32[idx];
    }
    const float scl = __ldg(&scale[br]);

    #pragma unroll
    for (int sub = 0; sub < 2; sub++) {
        const int gs = blockIdx.x * 64 + sub * 32;
        const int h  = gs / 800;

        __syncthreads();
        if (tid < 64) {
            int d = tid >> 3;
            float invS = 1.f / g_qs[(size_t)brb*64 + h*8 + d];
            ctx_s[tid] = g_ctx[((size_t)brb*NHEADS + h)*64 + tid] * invS;
        }
        if (tid >= 64 && tid < 72) m_s[tid - 64] = g_qm[(size_t)brb*64 + h*8 + (tid - 64)];
        __syncthreads();

        // Phase A
        {
            int g = tid >> 3, i = tid & 7;
            int np = gs + g;
            int n0 = (np % 800) * 8;
            const float* qp = g_q + ((size_t)brb*64 + h*8)*NPIX + n0 + i;
            float oo[8] = {0,0,0,0,0,0,0,0};
            #pragma unroll
            for (int d = 0; d < 8; d++) {
                float qv = __expf(qp[(size_t)d*NPIX] - m_s[d]);
                #pragma unroll
                for (int e = 0; e < 8; e++) oo[e] += qv * ctx_s[d*8 + e];
            }
            #pragma unroll
            for (int e = 0; e < 8; e++) out_s[g*OSS + i*8 + e] = oo[e];
        }
        __syncthreads();

        // Phase B via tf32 MMA; B frags pre-converted bits
        {
            const int warp = tid >> 5, lane = tid & 31;
            const int pmB = (warp & 1) * 16;
            const int pnB = (warp >> 1) * 16;
            const int gq = lane >> 2, tq = lane & 3;
            float dD[2][4] = {{0,0,0,0},{0,0,0,0}};
            #pragma unroll
            for (int ks = 0; ks < 8; ks++) {
                int k0 = ks*8;
                uint32_t a0 = f2tf32(out_s[(pmB+gq  )*OSS + k0+tq  ]);
                uint32_t a1 = f2tf32(out_s[(pmB+gq+8)*OSS + k0+tq  ]);
                uint32_t a2 = f2tf32(out_s[(pmB+gq  )*OSS + k0+tq+4]);
                uint32_t a3 = f2tf32(out_s[(pmB+gq+8)*OSS + k0+tq+4]);
                #pragma unroll
                for (int nf = 0; nf < 2; nf++) {
                    int nc = pnB + nf*8 + gq;
                    uint32_t b0 = wp[(k0+tq  )*WPS + nc];
                    uint32_t b1 = wp[(k0+tq+4)*WPS + nc];
                    mma_tf32(dD[nf], a0, a1, a2, a3, b0, b1);
                }
            }
            #pragma unroll
            for (int nf = 0; nf < 2; nf++) {
                int c0 = pnB + nf*8 + 2*tq;
                float bp0 = bproj[c0], bp1 = bproj[c0+1];
                float2 lo, hi;
                lo.x = __uint_as_float(f2tf32((dD[nf][0] + bp0)*scl));
                lo.y = __uint_as_float(f2tf32((dD[nf][1] + bp1)*scl));
                hi.x = __uint_as_float(f2tf32((dD[nf][2] + bp0)*scl));
                hi.y = __uint_as_float(f2tf32((dD[nf][3] + bp1)*scl));
                *(float2*)&p_s[(pmB+gq  )*OSS + c0] = lo;
                *(float2*)&p_s[(pmB+gq+8)*OSS + c0] = hi;
            }
        }
        __syncthreads();

        float* ap = g_att + (size_t)brb*64*NPIX;
        for (int idx = tid; idx < 64*8; idx += 256) {
            int o = idx >> 3, seg = idx & 7;
            float4 r;
            r.x = p_s[(seg*4 + 0)*OSS + o];
            r.y = p_s[(seg*4 + 1)*OSS + o];
            r.z = p_s[(seg*4 + 2)*OSS + o];
            r.w = p_s[(seg*4 + 3)*OSS + o];
            *(float4*)&ap[(size_t)o*NPIX + gs + seg*4] = r;
        }
    }
}

// ---------------- K6: final 256x256 GEMM via mma.sync tf32 --------------------
#define ASTR 36
#define BSTR 72
__global__ void final_kernel(const float* __restrict__ bf,
                             float* __restrict__ out)
{
    __shared__ uint32_t As[256*ASTR];
    __shared__ uint32_t Bs[32*BSTR];
    const int tid = threadIdx.x;
    const int n0  = blockIdx.x * 64;
    const int b   = blockIdx.y;

    const int warp = tid >> 5, lane = tid & 31;
    const int wo = (warp >> 1) * 64;
    const int wn = (warp & 1) * 32;
    const int g = lane >> 2, t = lane & 3;

    float d[4][4][4];
    #pragma unroll
    for (int mf = 0; mf < 4; mf++)
        #pragma unroll
        for (int nf = 0; nf < 4; nf++)
            #pragma unroll
            for (int r = 0; r < 4; r++) d[mf][nf][r] = 0.f;

    for (int kc = 0; kc < 256; kc += 32) {
        #pragma unroll
        for (int it = 0; it < 8; it++) {
            int idx = tid + it*256;
            int o = idx >> 3, k4 = (idx & 7) * 4;
            uint4 u = *(const uint4*)&g_wf32[o*256 + kc + k4];
            *(uint4*)&As[o*ASTR + k4] = u;
        }
        #pragma unroll
        for (int it = 0; it < 2; it++) {
            int idx = tid + it*256;
            int k = idx >> 4, n4 = (idx & 15) * 4;
            int kk = kc + k;
            uint4 u = *(const uint4*)&g_att[
                (((size_t)(kk >> 6)*NB + b)*64 + (kk & 63))*NPIX + n0 + n4];
            *(uint4*)&Bs[k*BSTR + n4] = u;
        }
        __syncthreads();

        #pragma unroll
        for (int kf = 0; kf < 4; kf++) {
            int k0 = kf*8;
            uint32_t a[4][4];
            #pragma unroll
            for (int mf = 0; mf < 4; mf++) {
                int orow = wo + mf*16 + g;
                a[mf][0] = As[(orow    )*ASTR + k0 + t];
                a[mf][1] = As[(orow + 8)*ASTR + k0 + t];
                a[mf][2] = As[(orow    )*ASTR + k0 + t + 4];
                a[mf][3] = As[(orow + 8)*ASTR + k0 + t + 4];
            }
            uint32_t bb[4][2];
            #pragma unroll
            for (int nf = 0; nf < 4; nf++) {
                int ncol = wn + nf*8 + g;
                bb[nf][0] = Bs[(k0 + t    )*BSTR + ncol];
                bb[nf][1] = Bs[(k0 + t + 4)*BSTR + ncol];
            }
            #pragma unroll
            for (int mf = 0; mf < 4; mf++)
                #pragma unroll
                for (int nf = 0; nf < 4; nf++)
                    mma_tf32(d[mf][nf], a[mf][0], a[mf][1], a[mf][2], a[mf][3],
                             bb[nf][0], bb[nf][1]);
        }
        __syncthreads();
    }

    #pragma unroll
    for (int mf = 0; mf < 4; mf++) {
        int o_lo = wo + mf*16 + g;
        int o_hi = o_lo + 8;
        float bf_lo = __ldg(&bf[o_lo]);
        float bf_hi = __ldg(&bf[o_hi]);
        float* base_lo = &out[((size_t)b*256 + o_lo)*NPIX + n0 + wn];
        float* base_hi = &out[((size_t)b*256 + o_hi)*NPIX + n0 + wn];
        #pragma unroll
        for (int nf = 0; nf < 4; nf++) {
            int nc = nf*8 + 2*t;
            float2 r0 = make_float2(d[mf][nf][0] + bf_lo, d[mf][nf][1] + bf_lo);
            float2 r1 = make_float2(d[mf][nf][2] + bf_hi, d[mf][nf][3] + bf_hi);
            *(float2*)&base_lo[nc] = r0;
            *(float2*)&base_hi[nc] = r1;
        }
    }
}

// ---------------- launch ---------------------------------------------------------
extern "C" void kernel_launch(void* const* d_in, const int* in_sizes, int n_in,
                              void* d_out, int out_size)
{
    const float* x     = (const float*)d_in[0];
    const float* w3    = (const float*)d_in[1];
    const float* b3    = (const float*)d_in[2];
    const float* w5    = (const float*)d_in[3];
    const float* b5    = (const float*)d_in[4];
    const float* w7    = (const float*)d_in[5];
    const float* b7    = (const float*)d_in[6];
    const float* w9    = (const float*)d_in[7];
    const float* b9    = (const float*)d_in[8];
    const float* wqkv  = (const float*)d_in[9];
    const float* wproj = (const float*)d_in[10];
    const float* bproj = (const float*)d_in[11];
    const float* wf    = (const float*)d_in[12];
    const float* bf    = (const float*)d_in[13];
    const float* scale = (const float*)d_in[14];
    float* out = (float*)d_out;

    prep_kernel<<<64, 1024>>>(wf, wproj, wqkv);
    dwconv_all_kernel<<<dim3(5, 256, 16), 320>>>(x, w3, b3, w5, b5, w7, b7, w9, b9);

    static bool attr_set = false;
    if (!attr_set) {
        cudaFuncSetAttribute(qkv_kernel,
                             cudaFuncAttributeMaxDynamicSharedMemorySize, 73728);
        attr_set = true;
    }
    qkv_kernel<<<dim3(100, 64), 256, 73728>>>();
    ctx_reduce_kernel<<<dim3(64, 25), 512>>>();
    qcombine_kernel<<<512, 256>>>();
    attn_out_kernel<<<dim3(100, 64), 256>>>(bproj, scale);
    final_kernel<<<dim3(100, 16), 256>>>(bf, out);
}

// round 14
// speedup vs baseline: 1.0014x; 1.0014x over previous
#include <cuda_runtime.h>
#include <cuda_bf16.h>
#include <cstdint>

#define BRANCHES 4
#define NB 16
#define CPB 64
#define HGT 80
#define WID 80
#define NPIX 6400
#define NHEADS 8
#define NTILES 100

// ---------------- scratch ----------------------------------------------------
__device__ float         g_y    [(size_t)BRANCHES*NB*CPB*NPIX];
__device__ __nv_bfloat16 g_qb   [(size_t)BRANCHES*NB*CPB*NPIX];   // raw q, bf16
__device__ float         g_ctx  [(size_t)BRANCHES*NB*NHEADS*64];
__device__ float         g_cpart[(size_t)NTILES*64*512];
__device__ float         g_pm   [(size_t)4096*NTILES];
__device__ float         g_ps   [(size_t)4096*NTILES];
__device__ float         g_qm   [(size_t)4096];
__device__ float         g_qs   [(size_t)4096];
__device__ float         g_att  [(size_t)BRANCHES*NB*CPB*NPIX];   // tf32-rounded
__device__ uint32_t      g_wf32 [65536];                           // wf as tf32 bits
__device__ uint32_t      g_wp32 [4096];                            // wproj as tf32 bits
__device__ uint32_t      g_wq_hi[192*32];                          // wqkv bf16-hi pairs
__device__ uint32_t      g_wq_lo[192*32];                          // wqkv bf16-lo pairs

// ---------------- helpers ------------------------------------------------------
__device__ __forceinline__ uint32_t f2tf32(float x) {
    uint32_t r;
    asm("cvt.rna.tf32.f32 %0, %1;" : "=r"(r) : "f"(x));
    return r;
}
__device__ __forceinline__ void mma_tf32(float d[4],
                                         uint32_t a0, uint32_t a1, uint32_t a2, uint32_t a3,
                                         uint32_t b0, uint32_t b1) {
    asm volatile(
        "mma.sync.aligned.m16n8k8.row.col.f32.tf32.tf32.f32 "
        "{%0,%1,%2,%3}, {%4,%5,%6,%7}, {%8,%9}, {%0,%1,%2,%3};"
        : "+f"(d[0]), "+f"(d[1]), "+f"(d[2]), "+f"(d[3])
        : "r"(a0), "r"(a1), "r"(a2), "r"(a3), "r"(b0), "r"(b1));
}
__device__ __forceinline__ void mma_bf16(float d[4],
                                         uint32_t a0, uint32_t a1, uint32_t a2, uint32_t a3,
                                         uint32_t b0, uint32_t b1) {
    asm volatile(
        "mma.sync.aligned.m16n8k16.row.col.f32.bf16.bf16.f32 "
        "{%0,%1,%2,%3}, {%4,%5,%6,%7}, {%8,%9}, {%0,%1,%2,%3};"
        : "+f"(d[0]), "+f"(d[1]), "+f"(d[2]), "+f"(d[3])
        : "r"(a0), "r"(a1), "r"(a2), "r"(a3), "r"(b0), "r"(b1));
}
__device__ __forceinline__ void bf16_split_pair(float f0, float f1,
                                                uint32_t& hi, uint32_t& lo) {
    __nv_bfloat162 hp = __floats2bfloat162_rn(f0, f1);
    float g0 = __bfloat162float(hp.x);
    float g1 = __bfloat162float(hp.y);
    __nv_bfloat162 lp = __floats2bfloat162_rn(f0 - g0, f1 - g1);
    hi = *reinterpret_cast<uint32_t*>(&hp);
    lo = *reinterpret_cast<uint32_t*>(&lp);
}

// ---------------- K0: prep ----------------------------------------------------
__global__ void prep_kernel(const float* __restrict__ wf,
                            const float* __restrict__ wproj,
                            const float* __restrict__ wqkv) {
    int i = blockIdx.x * 1024 + threadIdx.x;
    g_wf32[i] = f2tf32(wf[i]);
    if (i < 32768) g_ctx[i] = 0.f;
    if (i < 4096)  g_wp32[i] = f2tf32(wproj[i]);
    if (i < 6144) {
        int j = i >> 5, cp = i & 31;
        float w0 = wqkv[j*64 + 2*cp];
        float w1 = wqkv[j*64 + 2*cp + 1];
        uint32_t hi, lo;
        bf16_split_pair(w0, w1, hi, lo);
        g_wq_hi[i] = hi;
        g_wq_lo[i] = lo;
    }
}

// ---------------- K1: fused depthwise conv -------------------------------------
template<int KS>
__device__ __forceinline__ void dwconv_body(const float* __restrict__ x,
                                            const float* __restrict__ w,
                                            const float* __restrict__ bias,
                                            int br, int c, float* tile, float* wsm)
{
    const int b    = blockIdx.z;
    const int row0 = blockIdx.x * 16;
    const int tid  = threadIdx.x;

    if (tid < KS*KS) wsm[tid] = w[c*KS*KS + tid];
    const float bv = bias[c];
    const float* xp = x + ((size_t)b*256 + (size_t)br*64 + c) * NPIX;

    for (int idx = tid; idx < 24*88; idx += 320) {
        int r  = idx / 88, cl = idx % 88;
        int gh = row0 - 4 + r, gw = cl - 4;
        float v = 0.f;
        if (gh >= 0 && gh < HGT && gw >= 0 && gw < WID) v = xp[gh*WID + gw];
        tile[idx] = v;
    }
    __syncthreads();

    const int tx = tid % 20, ty = tid / 20;
    const int col0 = tx * 4;
    constexpr int PAD = KS / 2;
    constexpr int OFF = 4 - PAD;
    float a0 = 0.f, a1 = 0.f, a2 = 0.f, a3 = 0.f;
    float win[12];
    #pragma unroll
    for (int kh = 0; kh < KS; kh++) {
        int rb = (ty + 4 - PAD + kh)*88 + col0;
        float4 w0 = *(const float4*)&tile[rb];
        float4 w1 = *(const float4*)&tile[rb + 4];
        float4 w2 = *(const float4*)&tile[rb + 8];
        win[0]=w0.x; win[1]=w0.y; win[2]=w0.z;  win[3]=w0.w;
        win[4]=w1.x; win[5]=w1.y; win[6]=w1.z;  win[7]=w1.w;
        win[8]=w2.x; win[9]=w2.y; win[10]=w2.z; win[11]=w2.w;
        #pragma unroll
        for (int kw = 0; kw < KS; kw++) {
            float wv = wsm[kh*KS + kw];
            a0 += win[OFF + kw    ] * wv;
            a1 += win[OFF + kw + 1] * wv;
            a2 += win[OFF + kw + 2] * wv;
            a3 += win[OFF + kw + 3] * wv;
        }
    }
    int cb = (ty + 4)*88 + col0 + 4;
    float4 res = *(const float4*)&tile[cb];
    float* yp = g_y + (((size_t)br*NB + b)*CPB + c)*NPIX + (row0 + ty)*WID + col0;
    float4 r;
    r.x = fmaxf(a0 + bv + res.x, 0.f);
    r.y = fmaxf(a1 + bv + res.y, 0.f);
    r.z = fmaxf(a2 + bv + res.z, 0.f);
    r.w = fmaxf(a3 + bv + res.w, 0.f);
    *(float4*)yp = r;
}

__global__ void dwconv_all_kernel(const float* __restrict__ x,
                                  const float* __restrict__ w3, const float* __restrict__ b3,
                                  const float* __restrict__ w5, const float* __restrict__ b5,
                                  const float* __restrict__ w7, const float* __restrict__ b7,
                                  const float* __restrict__ w9, const float* __restrict__ b9)
{
    __shared__ float tile[24*88];
    __shared__ float wsm[81];
    const int br = blockIdx.y >> 6;
    const int c  = blockIdx.y & 63;
    switch (br) {
        case 0: dwconv_body<3>(x, w3, b3, 0, c, tile, wsm); break;
        case 1: dwconv_body<5>(x, w5, b5, 1, c, tile, wsm); break;
        case 2: dwconv_body<7>(x, w7, b7, 2, c, tile, wsm); break;
        default: dwconv_body<9>(x, w9, b9, 3, c, tile, wsm); break;
    }
}

// ---------------- K2: qkv bf16 3-term MMA + softmax/ctx/stats ------------------
#define QSTR 194
#define WQSU 36
#define YSS  72
__global__ void qkv_kernel()
{
    extern __shared__ uint32_t smu[];
    uint32_t* wqh = smu;
    uint32_t* wql = smu + 192*WQSU;
    float*    ys  = (float*)(smu + 13824);
    const int tid  = threadIdx.x;
    const int brb  = blockIdx.y;
    const int tile = blockIdx.x;
    const int n0   = tile * 64;

    const float* yp = g_y + (size_t)brb * CPB * NPIX;
    for (int idx = tid; idx < 1536; idx += 256) {
        int j = idx >> 3, w4 = (idx & 7) * 4;
        uint4 vh = *(const uint4*)&g_wq_hi[j*32 + w4];
        uint4 vl = *(const uint4*)&g_wq_lo[j*32 + w4];
        *(uint4*)&wqh[j*WQSU + w4] = vh;
        *(uint4*)&wql[j*WQSU + w4] = vl;
    }
    for (int idx = tid; idx < 1024; idx += 256) {
        int c = idx >> 4, t4 = (idx & 15) * 4;
        float4 v = *(const float4*)&yp[(size_t)c*NPIX + n0 + t4];
        *(float4*)&ys[c*YSS + t4] = v;
    }
    __syncthreads();

    const int warp = tid >> 5, lane = tid & 31;
    const int wm = (warp >> 2) * 96;
    const int wn = (warp & 3) * 16;
    const int g = lane >> 2, t = lane & 3;

    float d[6][2][4];
    #pragma unroll
    for (int mf = 0; mf < 6; mf++)
        #pragma unroll
        for (int nf = 0; nf < 2; nf++)
            #pragma unroll
            for (int r = 0; r < 4; r++) d[mf][nf][r] = 0.f;

    #pragma unroll
    for (int ks = 0; ks < 4; ks++) {
        const int k0 = ks * 16;
        const int ci = ks * 8 + t;
        uint32_t bh[2][2], bl[2][2];
        #pragma unroll
        for (int nf = 0; nf < 2; nf++) {
            int ncol = wn + nf*8 + g;
            float f0 = ys[(k0 + 2*t    )*YSS + ncol];
            float f1 = ys[(k0 + 2*t + 1)*YSS + ncol];
            float f2 = ys[(k0 + 2*t + 8)*YSS + ncol];
            float f3 = ys[(k0 + 2*t + 9)*YSS + ncol];
            bf16_split_pair(f0, f1, bh[nf][0], bl[nf][0]);
            bf16_split_pair(f2, f3, bh[nf][1], bl[nf][1]);
        }
        #pragma unroll
        for (int mf = 0; mf < 6; mf++) {
            int r0 = wm + mf*16 + g;
            uint32_t ah0 = wqh[(r0    )*WQSU + ci];
            uint32_t ah1 = wqh[(r0 + 8)*WQSU + ci];
            uint32_t ah2 = wqh[(r0    )*WQSU + ci + 4];
            uint32_t ah3 = wqh[(r0 + 8)*WQSU + ci + 4];
            uint32_t al0 = wql[(r0    )*WQSU + ci];
            uint32_t al1 = wql[(r0 + 8)*WQSU + ci];
            uint32_t al2 = wql[(r0    )*WQSU + ci + 4];
            uint32_t al3 = wql[(r0 + 8)*WQSU + ci + 4];
            #pragma unroll
            for (int nf = 0; nf < 2; nf++) {
                mma_bf16(d[mf][nf], ah0, ah1, ah2, ah3, bl[nf][0], bl[nf][1]);
                mma_bf16(d[mf][nf], al0, al1, al2, al3, bh[nf][0], bh[nf][1]);
                mma_bf16(d[mf][nf], ah0, ah1, ah2, ah3, bh[nf][0], bh[nf][1]);
            }
        }
    }
    __syncthreads();

    float* qkvs = (float*)smu;  // [t=64][j stride QSTR]
    #pragma unroll
    for (int mf = 0; mf < 6; mf++) {
        int r0 = wm + mf*16 + g;
        #pragma unroll
        for (int nf = 0; nf < 2; nf++) {
            int c0 = wn + nf*8 + 2*t;
            qkvs[(c0    )*QSTR + r0    ] = d[mf][nf][0];
            qkvs[(c0 + 1)*QSTR + r0    ] = d[mf][nf][1];
            qkvs[(c0    )*QSTR + r0 + 8] = d[mf][nf][2];
            qkvs[(c0 + 1)*QSTR + r0 + 8] = d[mf][nf][3];
        }
    }
    __syncthreads();

    // k softmax over head-dim (8)
    for (int th = tid; th < 512; th += 256) {
        int tt = th & 63, h = th >> 6;
        float* kr = &qkvs[tt*QSTR + 64 + h*8];
        float kv[8];
        #pragma unroll
        for (int dd = 0; dd < 8; dd++) kv[dd] = kr[dd];
        float m = kv[0];
        #pragma unroll
        for (int dd = 1; dd < 8; dd++) m = fmaxf(m, kv[dd]);
        float e[8]; float s = 0.f;
        #pragma unroll
        for (int dd = 0; dd < 8; dd++) { e[dd] = __expf(kv[dd] - m); s += e[dd]; }
        float inv = 1.f / s;
        #pragma unroll
        for (int dd = 0; dd < 8; dd++) kr[dd] = e[dd] * inv;
    }
    __syncthreads();

    // per-tile q stats
    {
        int hd = tid >> 2, part = tid & 3;
        float vals[16];
        #pragma unroll
        for (int i = 0; i < 16; i++) vals[i] = qkvs[(part*16 + i)*QSTR + hd];
        float m = vals[0];
        #pragma unroll
        for (int i = 1; i < 16; i++) m = fmaxf(m, vals[i]);
        m = fmaxf(m, __shfl_xor_sync(0xffffffffu, m, 1));
        m = fmaxf(m, __shfl_xor_sync(0xffffffffu, m, 2));
        float s = 0.f;
        #pragma unroll
        for (int i = 0; i < 16; i++) s += __expf(vals[i] - m);
        s += __shfl_xor_sync(0xffffffffu, s, 1);
        s += __shfl_xor_sync(0xffffffffu, s, 2);
        if (part == 0) {
            size_t r = (size_t)brb*64 + hd;
            g_pm[r*NTILES + tile] = m;
            g_ps[r*NTILES + tile] = s;
        }
    }

    // partial ctx
    {
        int h  = tid >> 5;
        int dd = (tid >> 2) & 7;
        int ep = tid & 3;
        float ce0 = 0.f, ce1 = 0.f;
        #pragma unroll 4
        for (int tt = 0; tt < 64; tt++) {
            float  kv = qkvs[tt*QSTR + 64 + h*8 + dd];
            float2 vv = *(const float2*)&qkvs[tt*QSTR + 128 + h*8 + 2*ep];
            ce0 += kv * vv.x;
            ce1 += kv * vv.y;
        }
        float2 r = make_float2(ce0, ce1);
        *(float2*)&g_cpart[((size_t)tile*64 + brb)*512 + h*64 + dd*8 + 2*ep] = r;
    }

    // q scatter (bf16)
    for (int idx = tid; idx < 1024; idx += 256) {
        int hd = idx >> 4, t4 = (idx & 15) * 4;
        __nv_bfloat162 p0 = __floats2bfloat162_rn(qkvs[(t4    )*QSTR + hd],
                                                  qkvs[(t4 + 1)*QSTR + hd]);
        __nv_bfloat162 p1 = __floats2bfloat162_rn(qkvs[(t4 + 2)*QSTR + hd],
                                                  qkvs[(t4 + 3)*QSTR + hd]);
        uint2 u;
        u.x = *reinterpret_cast<uint32_t*>(&p0);
        u.y = *reinterpret_cast<uint32_t*>(&p1);
        *(uint2*)&g_qb[((size_t)brb*64 + hd)*NPIX + n0 + t4] = u;
    }
}

// ---------------- K3a: reduce partial ctx (10-way over tiles) -----------------
// grid (64, 10), block 512
__global__ void ctx_reduce_kernel()
{
    const int brb = blockIdx.x;
    const int t0  = blockIdx.y * 10;
    const int tid = threadIdx.x;
    float s = 0.f;
    const float* p = g_cpart + (size_t)brb*512 + tid;
    #pragma unroll 5
    for (int t = 0; t < 10; t++)
        s += p[(size_t)(t0 + t)*64*512];
    atomicAdd(&g_ctx[(size_t)brb*512 + tid], s);
}

// ---------------- K3b: combine per-tile q stats (warp per row) ----------------
__global__ void qcombine_kernel()
{
    const int lane = threadIdx.x & 31;
    const int r    = blockIdx.x * 8 + (threadIdx.x >> 5);
    const float* pm = g_pm + (size_t)r*NTILES;
    const float* ps = g_ps + (size_t)r*NTILES;

    float mv[4]; float m = -1e30f;
    #pragma unroll
    for (int j = 0; j < 4; j++) {
        int t = lane + 32*j;
        mv[j] = (t < NTILES) ? pm[t] : -1e30f;
        m = fmaxf(m, mv[j]);
    }
    #pragma unroll
    for (int off = 16; off; off >>= 1)
        m = fmaxf(m, __shfl_xor_sync(0xffffffffu, m, off));

    float s = 0.f;
    #pragma unroll
    for (int j = 0; j < 4; j++) {
        int t = lane + 32*j;
        if (t < NTILES) s += ps[t] * __expf(mv[j] - m);
    }
    #pragma unroll
    for (int off = 16; off; off >>= 1)
        s += __shfl_xor_sync(0xffffffffu, s, off);

    if (lane == 0) { g_qm[r] = m; g_qs[r] = s; }
}

// ---------------- K5: softmax(q)@ctx, reshape, proj (tf32 MMA), scale ---------
#define WPS 72
#define OSS 68
__global__ void attn_out_kernel(const float* __restrict__ bproj,
                                const float* __restrict__ scale)
{
    __shared__ uint32_t wp [64*WPS];
    __shared__ float out_s[32*OSS];
    __shared__ float p_s  [32*OSS];
    __shared__ float ctx_s[64];
    __shared__ float m_s[8];
    const int tid = threadIdx.x;
    const int brb = blockIdx.y;
    const int br  = brb >> 4;

    for (int idx = tid; idx < 4096; idx += 256) {
        int o = idx >> 6, f = idx & 63;
        wp[f*WPS + o] = g_wp32[idx];
    }
    const float scl = __ldg(&scale[br]);

    #pragma unroll
    for (int sub = 0; sub < 2; sub++) {
        const int gs = blockIdx.x * 64 + sub * 32;
        const int h  = gs / 800;

        __syncthreads();
        if (tid < 64) {
            int d = tid >> 3;
            float invS = 1.f / g_qs[(size_t)brb*64 + h*8 + d];
            ctx_s[tid] = g_ctx[((size_t)brb*NHEADS + h)*64 + tid] * invS;
        }
        if (tid >= 64 && tid < 72) m_s[tid - 64] = g_qm[(size_t)brb*64 + h*8 + (tid - 64)];
        __syncthreads();

        // Phase A (q from bf16)
        {
            int g = tid >> 3, i = tid & 7;
            int np = gs + g;
            int n0 = (np % 800) * 8;
            const __nv_bfloat16* qp = g_qb + ((size_t)brb*64 + h*8)*NPIX + n0 + i;
            float oo[8] = {0,0,0,0,0,0,0,0};
            #pragma unroll
            for (int d = 0; d < 8; d++) {
                float qv = __expf(__bfloat162float(qp[(size_t)d*NPIX]) - m_s[d]);
                #pragma unroll
                for (int e = 0; e < 8; e++) oo[e] += qv * ctx_s[d*8 + e];
            }
            #pragma unroll
            for (int e = 0; e < 8; e++) out_s[g*OSS + i*8 + e] = oo[e];
        }
        __syncthreads();

        // Phase B via tf32 MMA; B frags pre-converted bits
        {
            const int warp = tid >> 5, lane = tid & 31;
            const int pmB = (warp & 1) * 16;
            const int pnB = (warp >> 1) * 16;
            const int gq = lane >> 2, tq = lane & 3;
            float dD[2][4] = {{0,0,0,0},{0,0,0,0}};
            #pragma unroll
            for (int ks = 0; ks < 8; ks++) {
                int k0 = ks*8;
                uint32_t a0 = f2tf32(out_s[(pmB+gq  )*OSS + k0+tq  ]);
                uint32_t a1 = f2tf32(out_s[(pmB+gq+8)*OSS + k0+tq  ]);
                uint32_t a2 = f2tf32(out_s[(pmB+gq  )*OSS + k0+tq+4]);
                uint32_t a3 = f2tf32(out_s[(pmB+gq+8)*OSS + k0+tq+4]);
                #pragma unroll
                for (int nf = 0; nf < 2; nf++) {
                    int nc = pnB + nf*8 + gq;
                    uint32_t b0 = wp[(k0+tq  )*WPS + nc];
                    uint32_t b1 = wp[(k0+tq+4)*WPS + nc];
                    mma_tf32(dD[nf], a0, a1, a2, a3, b0, b1);
                }
            }
            #pragma unroll
            for (int nf = 0; nf < 2; nf++) {
                int c0 = pnB + nf*8 + 2*tq;
                float bp0 = bproj[c0], bp1 = bproj[c0+1];
                float2 lo, hi;
                lo.x = __uint_as_float(f2tf32((dD[nf][0] + bp0)*scl));
                lo.y = __uint_as_float(f2tf32((dD[nf][1] + bp1)*scl));
                hi.x = __uint_as_float(f2tf32((dD[nf][2] + bp0)*scl));
                hi.y = __uint_as_float(f2tf32((dD[nf][3] + bp1)*scl));
                *(float2*)&p_s[(pmB+gq  )*OSS + c0] = lo;
                *(float2*)&p_s[(pmB+gq+8)*OSS + c0] = hi;
            }
        }
        __syncthreads();

        float* ap = g_att + (size_t)brb*64*NPIX;
        for (int idx = tid; idx < 64*8; idx += 256) {
            int o = idx >> 3, seg = idx & 7;
            float4 r;
            r.x = p_s[(seg*4 + 0)*OSS + o];
            r.y = p_s[(seg*4 + 1)*OSS + o];
            r.z = p_s[(seg*4 + 2)*OSS + o];
            r.w = p_s[(seg*4 + 3)*OSS + o];
            *(float4*)&ap[(size_t)o*NPIX + gs + seg*4] = r;
        }
    }
}

// ---------------- K6: final GEMM, 256o x 128n tile, 512 thr, tf32 MMA --------
#define ASTR 36
#define BSTRF 136
__global__ void final_kernel(const float* __restrict__ bf,
                             float* __restrict__ out)
{
    extern __shared__ uint32_t fsm[];
    uint32_t* As = fsm;               // [o=256][k=32] stride 36
    uint32_t* Bs = fsm + 256*ASTR;    // [k=32][n=128] stride 136
    const int tid = threadIdx.x;
    const int n0  = blockIdx.x * 128;
    const int b   = blockIdx.y;

    const int warp = tid >> 5, lane = tid & 31;
    const int wo = (warp >> 2) * 64;     // 4 o-groups
    const int wn = (warp & 3) * 32;      // 4 n-groups
    const int g = lane >> 2, t = lane & 3;

    float d[4][4][4];
    #pragma unroll
    for (int mf = 0; mf < 4; mf++)
        #pragma unroll
        for (int nf = 0; nf < 4; nf++)
            #pragma unroll
            for (int r = 0; r < 4; r++) d[mf][nf][r] = 0.f;

    for (int kc = 0; kc < 256; kc += 32) {
        // A: 8192 words = 2048 uint4 / 512 thr
        #pragma unroll
        for (int it = 0; it < 4; it++) {
            int idx = tid + it*512;
            int o = idx >> 3, k4 = (idx & 7) * 4;
            uint4 u = *(const uint4*)&g_wf32[o*256 + kc + k4];
            *(uint4*)&As[o*ASTR + k4] = u;
        }
        // B: 4096 words = 1024 uint4 / 512 thr
        #pragma unroll
        for (int it = 0; it < 2; it++) {
            int idx = tid + it*512;
            int k = idx >> 5, n4 = (idx & 31) * 4;
            int kk = kc + k;
            uint4 u = *(const uint4*)&g_att[
                (((size_t)(kk >> 6)*NB + b)*64 + (kk & 63))*NPIX + n0 + n4];
            *(uint4*)&Bs[k*BSTRF + n4] = u;
        }
        __syncthreads();

        #pragma unroll
        for (int kf = 0; kf < 4; kf++) {
            int k0 = kf*8;
            uint32_t a[4][4];
            #pragma unroll
            for (int mf = 0; mf < 4; mf++) {
                int orow = wo + mf*16 + g;
                a[mf][0] = As[(orow    )*ASTR + k0 + t];
                a[mf][1] = As[(orow + 8)*ASTR + k0 + t];
                a[mf][2] = As[(orow    )*ASTR + k0 + t + 4];
                a[mf][3] = As[(orow + 8)*ASTR + k0 + t + 4];
            }
            uint32_t bb[4][2];
            #pragma unroll
            for (int nf = 0; nf < 4; nf++) {
                int ncol = wn + nf*8 + g;
                bb[nf][0] = Bs[(k0 + t    )*BSTRF + ncol];
                bb[nf][1] = Bs[(k0 + t + 4)*BSTRF + ncol];
            }
            #pragma unroll
            for (int mf = 0; mf < 4; mf++)
                #pragma unroll
                for (int nf = 0; nf < 4; nf++)
                    mma_tf32(d[mf][nf], a[mf][0], a[mf][1], a[mf][2], a[mf][3],
                             bb[nf][0], bb[nf][1]);
        }
        __syncthreads();
    }

    #pragma unroll
    for (int mf = 0; mf < 4; mf++) {
        int o_lo = wo + mf*16 + g;
        int o_hi = o_lo + 8;
        float bf_lo = __ldg(&bf[o_lo]);
        float bf_hi = __ldg(&bf[o_hi]);
        float* base_lo = &out[((size_t)b*256 + o_lo)*NPIX + n0 + wn];
        float* base_hi = &out[((size_t)b*256 + o_hi)*NPIX + n0 + wn];
        #pragma unroll
        for (int nf = 0; nf < 4; nf++) {
            int nc = nf*8 + 2*t;
            float2 r0 = make_float2(d[mf][nf][0] + bf_lo, d[mf][nf][1] + bf_lo);
            float2 r1 = make_float2(d[mf][nf][2] + bf_hi, d[mf][nf][3] + bf_hi);
            *(float2*)&base_lo[nc] = r0;
            *(float2*)&base_hi[nc] = r1;
        }
    }
}

// ---------------- launch ---------------------------------------------------------
extern "C" void kernel_launch(void* const* d_in, const int* in_sizes, int n_in,
                              void* d_out, int out_size)
{
    const float* x     = (const float*)d_in[0];
    const float* w3    = (const float*)d_in[1];
    const float* b3    = (const float*)d_in[2];
    const float* w5    = (const float*)d_in[3];
    const float* b5    = (const float*)d_in[4];
    const float* w7    = (const float*)d_in[5];
    const float* b7    = (const float*)d_in[6];
    const float* w9    = (const float*)d_in[7];
    const float* b9    = (const float*)d_in[8];
    const float* wqkv  = (const float*)d_in[9];
    const float* wproj = (const float*)d_in[10];
    const float* bproj = (const float*)d_in[11];
    const float* wf    = (const float*)d_in[12];
    const float* bf    = (const float*)d_in[13];
    const float* scale = (const float*)d_in[14];
    float* out = (float*)d_out;

    prep_kernel<<<64, 1024>>>(wf, wproj, wqkv);
    dwconv_all_kernel<<<dim3(5, 256, 16), 320>>>(x, w3, b3, w5, b5, w7, b7, w9, b9);

    static bool attr_set = false;
    if (!attr_set) {
        cudaFuncSetAttribute(qkv_kernel,
                             cudaFuncAttributeMaxDynamicSharedMemorySize, 73728);
        cudaFuncSetAttribute(final_kernel,
                             cudaFuncAttributeMaxDynamicSharedMemorySize, 55296);
        attr_set = true;
    }
    qkv_kernel<<<dim3(100, 64), 256, 73728>>>();
    ctx_reduce_kernel<<<dim3(64, 10), 512>>>();
    qcombine_kernel<<<512, 256>>>();
    attn_out_kernel<<<dim3(100, 64), 256>>>(bproj, scale);
    final_kernel<<<dim3(50, 16), 512, 54272>>>(bf, out);
}

// round 15
// speedup vs baseline: 1.0151x; 1.0137x over previous
#include <cuda_runtime.h>
#include <cuda_bf16.h>
#include <cstdint>

#define BRANCHES 4
#define NB 16
#define CPB 64
#define HGT 80
#define WID 80
#define NPIX 6400
#define NHEADS 8
#define NTILES 100

// ---------------- scratch ----------------------------------------------------
__device__ float    g_y    [(size_t)BRANCHES*NB*CPB*NPIX];
__device__ float    g_q    [(size_t)BRANCHES*NB*CPB*NPIX];    // raw q
__device__ float    g_ctx  [(size_t)BRANCHES*NB*NHEADS*64];   // zeroed by prep, atomic acc
__device__ float    g_cpart[(size_t)NTILES*64*512];
__device__ float    g_pm   [(size_t)4096*NTILES];
__device__ float    g_ps   [(size_t)4096*NTILES];
__device__ float    g_qm   [(size_t)4096];
__device__ float    g_qs   [(size_t)4096];
__device__ float    g_att  [(size_t)BRANCHES*NB*CPB*NPIX];    // tf32-rounded
__device__ uint32_t g_wf32 [65536];                            // wf as tf32 bits
__device__ uint32_t g_wp32 [4096];                             // wproj as tf32 bits
__device__ uint32_t g_wq_hi[192*32];                           // wqkv bf16-hi pairs
__device__ uint32_t g_wq_lo[192*32];                           // wqkv bf16-lo pairs

// ---------------- helpers ------------------------------------------------------
__device__ __forceinline__ uint32_t f2tf32(float x) {
    uint32_t r;
    asm("cvt.rna.tf32.f32 %0, %1;" : "=r"(r) : "f"(x));
    return r;
}
__device__ __forceinline__ void mma_tf32(float d[4],
                                         uint32_t a0, uint32_t a1, uint32_t a2, uint32_t a3,
                                         uint32_t b0, uint32_t b1) {
    asm volatile(
        "mma.sync.aligned.m16n8k8.row.col.f32.tf32.tf32.f32 "
        "{%0,%1,%2,%3}, {%4,%5,%6,%7}, {%8,%9}, {%0,%1,%2,%3};"
        : "+f"(d[0]), "+f"(d[1]), "+f"(d[2]), "+f"(d[3])
        : "r"(a0), "r"(a1), "r"(a2), "r"(a3), "r"(b0), "r"(b1));
}
__device__ __forceinline__ void mma_bf16(float d[4],
                                         uint32_t a0, uint32_t a1, uint32_t a2, uint32_t a3,
                                         uint32_t b0, uint32_t b1) {
    asm volatile(
        "mma.sync.aligned.m16n8k16.row.col.f32.bf16.bf16.f32 "
        "{%0,%1,%2,%3}, {%4,%5,%6,%7}, {%8,%9}, {%0,%1,%2,%3};"
        : "+f"(d[0]), "+f"(d[1]), "+f"(d[2]), "+f"(d[3])
        : "r"(a0), "r"(a1), "r"(a2), "r"(a3), "r"(b0), "r"(b1));
}
__device__ __forceinline__ void bf16_split_pair(float f0, float f1,
                                                uint32_t& hi, uint32_t& lo) {
    __nv_bfloat162 hp = __floats2bfloat162_rn(f0, f1);
    float g0 = __bfloat162float(hp.x);
    float g1 = __bfloat162float(hp.y);
    __nv_bfloat162 lp = __floats2bfloat162_rn(f0 - g0, f1 - g1);
    hi = *reinterpret_cast<uint32_t*>(&hp);
    lo = *reinterpret_cast<uint32_t*>(&lp);
}

// ---------------- K0: prep ----------------------------------------------------
__global__ void prep_kernel(const float* __restrict__ wf,
                            const float* __restrict__ wproj,
                            const float* __restrict__ wqkv) {
    int i = blockIdx.x * 1024 + threadIdx.x;
    g_wf32[i] = f2tf32(wf[i]);
    if (i < 32768) g_ctx[i] = 0.f;
    if (i < 4096)  g_wp32[i] = f2tf32(wproj[i]);
    if (i < 6144) {
        int j = i >> 5, cp = i & 31;
        float w0 = wqkv[j*64 + 2*cp];
        float w1 = wqkv[j*64 + 2*cp + 1];
        uint32_t hi, lo;
        bf16_split_pair(w0, w1, hi, lo);
        g_wq_hi[i] = hi;
        g_wq_lo[i] = lo;
    }
}

// ---------------- K1: fused depthwise conv -------------------------------------
template<int KS>
__device__ __forceinline__ void dwconv_body(const float* __restrict__ x,
                                            const float* __restrict__ w,
                                            const float* __restrict__ bias,
                                            int br, int c, float* tile, float* wsm)
{
    const int b    = blockIdx.z;
    const int row0 = blockIdx.x * 16;
    const int tid  = threadIdx.x;

    if (tid < KS*KS) wsm[tid] = w[c*KS*KS + tid];
    const float bv = bias[c];
    const float* xp = x + ((size_t)b*256 + (size_t)br*64 + c) * NPIX;

    for (int idx = tid; idx < 24*88; idx += 320) {
        int r  = idx / 88, cl = idx % 88;
        int gh = row0 - 4 + r, gw = cl - 4;
        float v = 0.f;
        if (gh >= 0 && gh < HGT && gw >= 0 && gw < WID) v = xp[gh*WID + gw];
        tile[idx] = v;
    }
    __syncthreads();

    const int tx = tid % 20, ty = tid / 20;
    const int col0 = tx * 4;
    constexpr int PAD = KS / 2;
    constexpr int OFF = 4 - PAD;
    float a0 = 0.f, a1 = 0.f, a2 = 0.f, a3 = 0.f;
    float win[12];
    #pragma unroll
    for (int kh = 0; kh < KS; kh++) {
        int rb = (ty + 4 - PAD + kh)*88 + col0;
        float4 w0 = *(const float4*)&tile[rb];
        float4 w1 = *(const float4*)&tile[rb + 4];
        float4 w2 = *(const float4*)&tile[rb + 8];
        win[0]=w0.x; win[1]=w0.y; win[2]=w0.z;  win[3]=w0.w;
        win[4]=w1.x; win[5]=w1.y; win[6]=w1.z;  win[7]=w1.w;
        win[8]=w2.x; win[9]=w2.y; win[10]=w2.z; win[11]=w2.w;
        #pragma unroll
        for (int kw = 0; kw < KS; kw++) {
            float wv = wsm[kh*KS + kw];
            a0 += win[OFF + kw    ] * wv;
            a1 += win[OFF + kw + 1] * wv;
            a2 += win[OFF + kw + 2] * wv;
            a3 += win[OFF + kw + 3] * wv;
        }
    }
    int cb = (ty + 4)*88 + col0 + 4;
    float4 res = *(const float4*)&tile[cb];
    float* yp = g_y + (((size_t)br*NB + b)*CPB + c)*NPIX + (row0 + ty)*WID + col0;
    float4 r;
    r.x = fmaxf(a0 + bv + res.x, 0.f);
    r.y = fmaxf(a1 + bv + res.y, 0.f);
    r.z = fmaxf(a2 + bv + res.z, 0.f);
    r.w = fmaxf(a3 + bv + res.w, 0.f);
    *(float4*)yp = r;
}

__global__ void dwconv_all_kernel(const float* __restrict__ x,
                                  const float* __restrict__ w3, const float* __restrict__ b3,
                                  const float* __restrict__ w5, const float* __restrict__ b5,
                                  const float* __restrict__ w7, const float* __restrict__ b7,
                                  const float* __restrict__ w9, const float* __restrict__ b9)
{
    __shared__ float tile[24*88];
    __shared__ float wsm[81];
    const int br = blockIdx.y >> 6;
    const int c  = blockIdx.y & 63;
    switch (br) {
        case 0: dwconv_body<3>(x, w3, b3, 0, c, tile, wsm); break;
        case 1: dwconv_body<5>(x, w5, b5, 1, c, tile, wsm); break;
        case 2: dwconv_body<7>(x, w7, b7, 2, c, tile, wsm); break;
        default: dwconv_body<9>(x, w9, b9, 3, c, tile, wsm); break;
    }
}

// ---------------- K2: qkv via bf16 3-term MMA + softmax/ctx/stats (R11) --------
#define QSTR 194
#define WQSU 36
#define YSS  72
__global__ void qkv_kernel()
{
    extern __shared__ uint32_t smu[];
    uint32_t* wqh = smu;
    uint32_t* wql = smu + 192*WQSU;
    float*    ys  = (float*)(smu + 13824);
    const int tid  = threadIdx.x;
    const int brb  = blockIdx.y;
    const int tile = blockIdx.x;
    const int n0   = tile * 64;

    const float* yp = g_y + (size_t)brb * CPB * NPIX;
    for (int idx = tid; idx < 1536; idx += 256) {
        int j = idx >> 3, w4 = (idx & 7) * 4;
        uint4 vh = *(const uint4*)&g_wq_hi[j*32 + w4];
        uint4 vl = *(const uint4*)&g_wq_lo[j*32 + w4];
        *(uint4*)&wqh[j*WQSU + w4] = vh;
        *(uint4*)&wql[j*WQSU + w4] = vl;
    }
    for (int idx = tid; idx < 1024; idx += 256) {
        int c = idx >> 4, t4 = (idx & 15) * 4;
        float4 v = *(const float4*)&yp[(size_t)c*NPIX + n0 + t4];
        *(float4*)&ys[c*YSS + t4] = v;
    }
    __syncthreads();

    const int warp = tid >> 5, lane = tid & 31;
    const int wm = (warp >> 2) * 96;
    const int wn = (warp & 3) * 16;
    const int g = lane >> 2, t = lane & 3;

    float d[6][2][4];
    #pragma unroll
    for (int mf = 0; mf < 6; mf++)
        #pragma unroll
        for (int nf = 0; nf < 2; nf++)
            #pragma unroll
            for (int r = 0; r < 4; r++) d[mf][nf][r] = 0.f;

    #pragma unroll
    for (int ks = 0; ks < 4; ks++) {
        const int k0 = ks * 16;
        const int ci = ks * 8 + t;
        uint32_t bh[2][2], bl[2][2];
        #pragma unroll
        for (int nf = 0; nf < 2; nf++) {
            int ncol = wn + nf*8 + g;
            float f0 = ys[(k0 + 2*t    )*YSS + ncol];
            float f1 = ys[(k0 + 2*t + 1)*YSS + ncol];
            float f2 = ys[(k0 + 2*t + 8)*YSS + ncol];
            float f3 = ys[(k0 + 2*t + 9)*YSS + ncol];
            bf16_split_pair(f0, f1, bh[nf][0], bl[nf][0]);
            bf16_split_pair(f2, f3, bh[nf][1], bl[nf][1]);
        }
        #pragma unroll
        for (int mf = 0; mf < 6; mf++) {
            int r0 = wm + mf*16 + g;
            uint32_t ah0 = wqh[(r0    )*WQSU + ci];
            uint32_t ah1 = wqh[(r0 + 8)*WQSU + ci];
            uint32_t ah2 = wqh[(r0    )*WQSU + ci + 4];
            uint32_t ah3 = wqh[(r0 + 8)*WQSU + ci + 4];
            uint32_t al0 = wql[(r0    )*WQSU + ci];
            uint32_t al1 = wql[(r0 + 8)*WQSU + ci];
            uint32_t al2 = wql[(r0    )*WQSU + ci + 4];
            uint32_t al3 = wql[(r0 + 8)*WQSU + ci + 4];
            #pragma unroll
            for (int nf = 0; nf < 2; nf++) {
                mma_bf16(d[mf][nf], ah0, ah1, ah2, ah3, bl[nf][0], bl[nf][1]);
                mma_bf16(d[mf][nf], al0, al1, al2, al3, bh[nf][0], bh[nf][1]);
                mma_bf16(d[mf][nf], ah0, ah1, ah2, ah3, bh[nf][0], bh[nf][1]);
            }
        }
    }
    __syncthreads();

    float* qkvs = (float*)smu;  // [t=64][j stride QSTR]
    #pragma unroll
    for (int mf = 0; mf < 6; mf++) {
        int r0 = wm + mf*16 + g;
        #pragma unroll
        for (int nf = 0; nf < 2; nf++) {
            int c0 = wn + nf*8 + 2*t;
            qkvs[(c0    )*QSTR + r0    ] = d[mf][nf][0];
            qkvs[(c0 + 1)*QSTR + r0    ] = d[mf][nf][1];
            qkvs[(c0    )*QSTR + r0 + 8] = d[mf][nf][2];
            qkvs[(c0 + 1)*QSTR + r0 + 8] = d[mf][nf][3];
        }
    }
    __syncthreads();

    // k softmax over head-dim (8)
    for (int th = tid; th < 512; th += 256) {
        int tt = th & 63, h = th >> 6;
        float* kr = &qkvs[tt*QSTR + 64 + h*8];
        float kv[8];
        #pragma unroll
        for (int dd = 0; dd < 8; dd++) kv[dd] = kr[dd];
        float m = kv[0];
        #pragma unroll
        for (int dd = 1; dd < 8; dd++) m = fmaxf(m, kv[dd]);
        float e[8]; float s = 0.f;
        #pragma unroll
        for (int dd = 0; dd < 8; dd++) { e[dd] = __expf(kv[dd] - m); s += e[dd]; }
        float inv = 1.f / s;
        #pragma unroll
        for (int dd = 0; dd < 8; dd++) kr[dd] = e[dd] * inv;
    }
    __syncthreads();

    // per-tile q stats
    {
        int hd = tid >> 2, part = tid & 3;
        float vals[16];
        #pragma unroll
        for (int i = 0; i < 16; i++) vals[i] = qkvs[(part*16 + i)*QSTR + hd];
        float m = vals[0];
        #pragma unroll
        for (int i = 1; i < 16; i++) m = fmaxf(m, vals[i]);
        m = fmaxf(m, __shfl_xor_sync(0xffffffffu, m, 1));
        m = fmaxf(m, __shfl_xor_sync(0xffffffffu, m, 2));
        float s = 0.f;
        #pragma unroll
        for (int i = 0; i < 16; i++) s += __expf(vals[i] - m);
        s += __shfl_xor_sync(0xffffffffu, s, 1);
        s += __shfl_xor_sync(0xffffffffu, s, 2);
        if (part == 0) {
            size_t r = (size_t)brb*64 + hd;
            g_pm[r*NTILES + tile] = m;
            g_ps[r*NTILES + tile] = s;
        }
    }

    // partial ctx
    {
        int h  = tid >> 5;
        int dd = (tid >> 2) & 7;
        int ep = tid & 3;
        float ce0 = 0.f, ce1 = 0.f;
        #pragma unroll 4
        for (int tt = 0; tt < 64; tt++) {
            float  kv = qkvs[tt*QSTR + 64 + h*8 + dd];
            float2 vv = *(const float2*)&qkvs[tt*QSTR + 128 + h*8 + 2*ep];
            ce0 += kv * vv.x;
            ce1 += kv * vv.y;
        }
        float2 r = make_float2(ce0, ce1);
        *(float2*)&g_cpart[((size_t)tile*64 + brb)*512 + h*64 + dd*8 + 2*ep] = r;
    }

    // q scatter
    for (int idx = tid; idx < 1024; idx += 256) {
        int hd = idx >> 4, t4 = (idx & 15) * 4;
        float4 v;
        v.x = qkvs[(t4    )*QSTR + hd];
        v.y = qkvs[(t4 + 1)*QSTR + hd];
        v.z = qkvs[(t4 + 2)*QSTR + hd];
        v.w = qkvs[(t4 + 3)*QSTR + hd];
        *(float4*)&g_q[((size_t)brb*64 + hd)*NPIX + n0 + t4] = v;
    }
}

// ---------------- K3: merged ctx reduce + q stats combine ---------------------
// grid (64, 14), block 512.
//   y in [0,10): ctx partial-sum (brb = x, tiles [y*10, y*10+10))
//   y in [10,14): qcombine, block q = x + (y-10)*64, 16 warps -> 16 rows
__global__ void reduce_combine_kernel()
{
    const int tid = threadIdx.x;
    if (blockIdx.y < 10) {
        const int brb = blockIdx.x;
        const int t0  = blockIdx.y * 10;
        float s = 0.f;
        const float* p = g_cpart + (size_t)brb*512 + tid;
        #pragma unroll 5
        for (int t = 0; t < 10; t++)
            s += p[(size_t)(t0 + t)*64*512];
        atomicAdd(&g_ctx[(size_t)brb*512 + tid], s);
    } else {
        const int lane = tid & 31;
        const int q    = blockIdx.x + (blockIdx.y - 10) * 64;   // 0..255
        const int r    = q * 16 + (tid >> 5);                    // 4096 rows
        const float* pm = g_pm + (size_t)r*NTILES;
        const float* ps = g_ps + (size_t)r*NTILES;

        float mv[4]; float m = -1e30f;
        #pragma unroll
        for (int j = 0; j < 4; j++) {
            int t = lane + 32*j;
            mv[j] = (t < NTILES) ? pm[t] : -1e30f;
            m = fmaxf(m, mv[j]);
        }
        #pragma unroll
        for (int off = 16; off; off >>= 1)
            m = fmaxf(m, __shfl_xor_sync(0xffffffffu, m, off));

        float s = 0.f;
        #pragma unroll
        for (int j = 0; j < 4; j++) {
            int t = lane + 32*j;
            if (t < NTILES) s += ps[t] * __expf(mv[j] - m);
        }
        #pragma unroll
        for (int off = 16; off; off >>= 1)
            s += __shfl_xor_sync(0xffffffffu, s, off);

        if (lane == 0) { g_qm[r] = m; g_qs[r] = s; }
    }
}

// ---------------- K5: softmax(q)@ctx, reshape, proj (tf32 MMA), scale (R11) ---
#define WPS 72
#define OSS 68
__global__ void attn_out_kernel(const float* __restrict__ bproj,
                                const float* __restrict__ scale)
{
    __shared__ uint32_t wp [64*WPS];
    __shared__ float out_s[32*OSS];
    __shared__ float p_s  [32*OSS];
    __shared__ float ctx_s[64];
    __shared__ float m_s[8];
    const int tid = threadIdx.x;
    const int brb = blockIdx.y;
    const int br  = brb >> 4;

    for (int idx = tid; idx < 4096; idx += 256) {
        int o = idx >> 6, f = idx & 63;
        wp[f*WPS + o] = g_wp32[idx];
    }
    const float scl = __ldg(&scale[br]);

    #pragma unroll
    for (int sub = 0; sub < 2; sub++) {
        const int gs = blockIdx.x * 64 + sub * 32;
        const int h  = gs / 800;

        __syncthreads();
        if (tid < 64) {
            int d = tid >> 3;
            float invS = 1.f / g_qs[(size_t)brb*64 + h*8 + d];
            ctx_s[tid] = g_ctx[((size_t)brb*NHEADS + h)*64 + tid] * invS;
        }
        if (tid >= 64 && tid < 72) m_s[tid - 64] = g_qm[(size_t)brb*64 + h*8 + (tid - 64)];
        __syncthreads();

        // Phase A
        {
            int g = tid >> 3, i = tid & 7;
            int np = gs + g;
            int n0 = (np % 800) * 8;
            const float* qp = g_q + ((size_t)brb*64 + h*8)*NPIX + n0 + i;
            float oo[8] = {0,0,0,0,0,0,0,0};
            #pragma unroll
            for (int d = 0; d < 8; d++) {
                float qv = __expf(qp[(size_t)d*NPIX] - m_s[d]);
                #pragma unroll
                for (int e = 0; e < 8; e++) oo[e] += qv * ctx_s[d*8 + e];
            }
            #pragma unroll
            for (int e = 0; e < 8; e++) out_s[g*OSS + i*8 + e] = oo[e];
        }
        __syncthreads();

        // Phase B via tf32 MMA; B frags pre-converted bits
        {
            const int warp = tid >> 5, lane = tid & 31;
            const int pmB = (warp & 1) * 16;
            const int pnB = (warp >> 1) * 16;
            const int gq = lane >> 2, tq = lane & 3;
            float dD[2][4] = {{0,0,0,0},{0,0,0,0}};
            #pragma unroll
            for (int ks = 0; ks < 8; ks++) {
                int k0 = ks*8;
                uint32_t a0 = f2tf32(out_s[(pmB+gq  )*OSS + k0+tq  ]);
                uint32_t a1 = f2tf32(out_s[(pmB+gq+8)*OSS + k0+tq  ]);
                uint32_t a2 = f2tf32(out_s[(pmB+gq  )*OSS + k0+tq+4]);
                uint32_t a3 = f2tf32(out_s[(pmB+gq+8)*OSS + k0+tq+4]);
                #pragma unroll
                for (int nf = 0; nf < 2; nf++) {
                    int nc = pnB + nf*8 + gq;
                    uint32_t b0 = wp[(k0+tq  )*WPS + nc];
                    uint32_t b1 = wp[(k0+tq+4)*WPS + nc];
                    mma_tf32(dD[nf], a0, a1, a2, a3, b0, b1);
                }
            }
            #pragma unroll
            for (int nf = 0; nf < 2; nf++) {
                int c0 = pnB + nf*8 + 2*tq;
                float bp0 = bproj[c0], bp1 = bproj[c0+1];
                float2 lo, hi;
                lo.x = __uint_as_float(f2tf32((dD[nf][0] + bp0)*scl));
                lo.y = __uint_as_float(f2tf32((dD[nf][1] + bp1)*scl));
                hi.x = __uint_as_float(f2tf32((dD[nf][2] + bp0)*scl));
                hi.y = __uint_as_float(f2tf32((dD[nf][3] + bp1)*scl));
                *(float2*)&p_s[(pmB+gq  )*OSS + c0] = lo;
                *(float2*)&p_s[(pmB+gq+8)*OSS + c0] = hi;
            }
        }
        __syncthreads();

        float* ap = g_att + (size_t)brb*64*NPIX;
        for (int idx = tid; idx < 64*8; idx += 256) {
            int o = idx >> 3, seg = idx & 7;
            float4 r;
            r.x = p_s[(seg*4 + 0)*OSS + o];
            r.y = p_s[(seg*4 + 1)*OSS + o];
            r.z = p_s[(seg*4 + 2)*OSS + o];
            r.w = p_s[(seg*4 + 3)*OSS + o];
            *(float4*)&ap[(size_t)o*NPIX + gs + seg*4] = r;
        }
    }
}

// ---------------- K6: final 256x256 GEMM via mma.sync tf32 (R11) --------------
#define ASTR 36
#define BSTR 72
__global__ void final_kernel(const float* __restrict__ bf,
                             float* __restrict__ out)
{
    __shared__ uint32_t As[256*ASTR];
    __shared__ uint32_t Bs[32*BSTR];
    const int tid = threadIdx.x;
    const int n0  = blockIdx.x * 64;
    const int b   = blockIdx.y;

    const int warp = tid >> 5, lane = tid & 31;
    const int wo = (warp >> 1) * 64;
    const int wn = (warp & 1) * 32;
    const int g = lane >> 2, t = lane & 3;

    float d[4][4][4];
    #pragma unroll
    for (int mf = 0; mf < 4; mf++)
        #pragma unroll
        for (int nf = 0; nf < 4; nf++)
            #pragma unroll
            for (int r = 0; r < 4; r++) d[mf][nf][r] = 0.f;

    for (int kc = 0; kc < 256; kc += 32) {
        #pragma unroll
        for (int it = 0; it < 8; it++) {
            int idx = tid + it*256;
            int o = idx >> 3, k4 = (idx & 7) * 4;
            uint4 u = *(const uint4*)&g_wf32[o*256 + kc + k4];
            *(uint4*)&As[o*ASTR + k4] = u;
        }
        #pragma unroll
        for (int it = 0; it < 2; it++) {
            int idx = tid + it*256;
            int k = idx >> 4, n4 = (idx & 15) * 4;
            int kk = kc + k;
            uint4 u = *(const uint4*)&g_att[
                (((size_t)(kk >> 6)*NB + b)*64 + (kk & 63))*NPIX + n0 + n4];
            *(uint4*)&Bs[k*BSTR + n4] = u;
        }
        __syncthreads();

        #pragma unroll
        for (int kf = 0; kf < 4; kf++) {
            int k0 = kf*8;
            uint32_t a[4][4];
            #pragma unroll
            for (int mf = 0; mf < 4; mf++) {
                int orow = wo + mf*16 + g;
                a[mf][0] = As[(orow    )*ASTR + k0 + t];
                a[mf][1] = As[(orow + 8)*ASTR + k0 + t];
                a[mf][2] = As[(orow    )*ASTR + k0 + t + 4];
                a[mf][3] = As[(orow + 8)*ASTR + k0 + t + 4];
            }
            uint32_t bb[4][2];
            #pragma unroll
            for (int nf = 0; nf < 4; nf++) {
                int ncol = wn + nf*8 + g;
                bb[nf][0] = Bs[(k0 + t    )*BSTR + ncol];
                bb[nf][1] = Bs[(k0 + t + 4)*BSTR + ncol];
            }
            #pragma unroll
            for (int mf = 0; mf < 4; mf++)
                #pragma unroll
                for (int nf = 0; nf < 4; nf++)
                    mma_tf32(d[mf][nf], a[mf][0], a[mf][1], a[mf][2], a[mf][3],
                             bb[nf][0], bb[nf][1]);
        }
        __syncthreads();
    }

    #pragma unroll
    for (int mf = 0; mf < 4; mf++) {
        int o_lo = wo + mf*16 + g;
        int o_hi = o_lo + 8;
        float bf_lo = __ldg(&bf[o_lo]);
        float bf_hi = __ldg(&bf[o_hi]);
        float* base_lo = &out[((size_t)b*256 + o_lo)*NPIX + n0 + wn];
        float* base_hi = &out[((size_t)b*256 + o_hi)*NPIX + n0 + wn];
        #pragma unroll
        for (int nf = 0; nf < 4; nf++) {
            int nc = nf*8 + 2*t;
            float2 r0 = make_float2(d[mf][nf][0] + bf_lo, d[mf][nf][1] + bf_lo);
            float2 r1 = make_float2(d[mf][nf][2] + bf_hi, d[mf][nf][3] + bf_hi);
            *(float2*)&base_lo[nc] = r0;
            *(float2*)&base_hi[nc] = r1;
        }
    }
}

// ---------------- launch ---------------------------------------------------------
extern "C" void kernel_launch(void* const* d_in, const int* in_sizes, int n_in,
                              void* d_out, int out_size)
{
    const float* x     = (const float*)d_in[0];
    const float* w3    = (const float*)d_in[1];
    const float* b3    = (const float*)d_in[2];
    const float* w5    = (const float*)d_in[3];
    const float* b5    = (const float*)d_in[4];
    const float* w7    = (const float*)d_in[5];
    const float* b7    = (const float*)d_in[6];
    const float* w9    = (const float*)d_in[7];
    const float* b9    = (const float*)d_in[8];
    const float* wqkv  = (const float*)d_in[9];
    const float* wproj = (const float*)d_in[10];
    const float* bproj = (const float*)d_in[11];
    const float* wf    = (const float*)d_in[12];
    const float* bf    = (const float*)d_in[13];
    const float* scale = (const float*)d_in[14];
    float* out = (float*)d_out;

    prep_kernel<<<64, 1024>>>(wf, wproj, wqkv);
    dwconv_all_kernel<<<dim3(5, 256, 16), 320>>>(x, w3, b3, w5, b5, w7, b7, w9, b9);

    static bool attr_set = false;
    if (!attr_set) {
        cudaFuncSetAttribute(qkv_kernel,
                             cudaFuncAttributeMaxDynamicSharedMemorySize, 73728);
        attr_set = true;
    }
    qkv_kernel<<<dim3(100, 64), 256, 73728>>>();
    reduce_combine_kernel<<<dim3(64, 14), 512>>>();
    attn_out_kernel<<<dim3(100, 64), 256>>>(bproj, scale);
    final_kernel<<<dim3(100, 16), 256>>>(bf, out);
}

// round 16
// speedup vs baseline: 1.0310x; 1.0156x over previous
#include <cuda_runtime.h>
#include <cuda_bf16.h>
#include <cstdint>

#define BRANCHES 4
#define NB 16
#define CPB 64
#define HGT 80
#define WID 80
#define NPIX 6400
#define NHEADS 8
#define NTILES 100

// ---------------- scratch ----------------------------------------------------
__device__ float    g_y    [(size_t)BRANCHES*NB*CPB*NPIX];
__device__ float    g_q    [(size_t)BRANCHES*NB*CPB*NPIX];    // raw q
__device__ float    g_ctx  [(size_t)BRANCHES*NB*NHEADS*64];   // zeroed in prep slice
__device__ float    g_cpart[(size_t)NTILES*64*512];
__device__ float    g_pm   [(size_t)4096*NTILES];
__device__ float    g_ps   [(size_t)4096*NTILES];
__device__ float    g_qm   [(size_t)4096];
__device__ float    g_qs   [(size_t)4096];
__device__ float    g_att  [(size_t)BRANCHES*NB*CPB*NPIX];    // tf32-rounded
__device__ uint32_t g_wf32 [65536];                            // wf as tf32 bits
__device__ uint32_t g_wp32 [4096];                             // wproj as tf32 bits
__device__ uint32_t g_wq_hi[192*32];                           // wqkv bf16-hi pairs
__device__ uint32_t g_wq_lo[192*32];                           // wqkv bf16-lo pairs

// ---------------- helpers ------------------------------------------------------
__device__ __forceinline__ uint32_t f2tf32(float x) {
    uint32_t r;
    asm("cvt.rna.tf32.f32 %0, %1;" : "=r"(r) : "f"(x));
    return r;
}
__device__ __forceinline__ void mma_tf32(float d[4],
                                         uint32_t a0, uint32_t a1, uint32_t a2, uint32_t a3,
                                         uint32_t b0, uint32_t b1) {
    asm volatile(
        "mma.sync.aligned.m16n8k8.row.col.f32.tf32.tf32.f32 "
        "{%0,%1,%2,%3}, {%4,%5,%6,%7}, {%8,%9}, {%0,%1,%2,%3};"
        : "+f"(d[0]), "+f"(d[1]), "+f"(d[2]), "+f"(d[3])
        : "r"(a0), "r"(a1), "r"(a2), "r"(a3), "r"(b0), "r"(b1));
}
__device__ __forceinline__ void mma_bf16(float d[4],
                                         uint32_t a0, uint32_t a1, uint32_t a2, uint32_t a3,
                                         uint32_t b0, uint32_t b1) {
    asm volatile(
        "mma.sync.aligned.m16n8k16.row.col.f32.bf16.bf16.f32 "
        "{%0,%1,%2,%3}, {%4,%5,%6,%7}, {%8,%9}, {%0,%1,%2,%3};"
        : "+f"(d[0]), "+f"(d[1]), "+f"(d[2]), "+f"(d[3])
        : "r"(a0), "r"(a1), "r"(a2), "r"(a3), "r"(b0), "r"(b1));
}
__device__ __forceinline__ void bf16_split_pair(float f0, float f1,
                                                uint32_t& hi, uint32_t& lo) {
    __nv_bfloat162 hp = __floats2bfloat162_rn(f0, f1);
    float g0 = __bfloat162float(hp.x);
    float g1 = __bfloat162float(hp.y);
    __nv_bfloat162 lp = __floats2bfloat162_rn(f0 - g0, f1 - g1);
    hi = *reinterpret_cast<uint32_t*>(&hp);
    lo = *reinterpret_cast<uint32_t*>(&lp);
}

// ---------------- K1: fused depthwise conv + prep slice -------------------------
template<int KS>
__device__ __forceinline__ void dwconv_body(const float* __restrict__ x,
                                            const float* __restrict__ w,
                                            const float* __restrict__ bias,
                                            int br, int c, float* tile, float* wsm)
{
    const int b    = blockIdx.z;
    const int row0 = blockIdx.x * 16;
    const int tid  = threadIdx.x;

    if (tid < KS*KS) wsm[tid] = w[c*KS*KS + tid];
    const float bv = bias[c];
    const float* xp = x + ((size_t)b*256 + (size_t)br*64 + c) * NPIX;

    // halo stage with incremental row/col indexing (no per-iter div/mod)
    {
        int r  = tid / 88;
        int cl = tid - r * 88;
        #pragma unroll
        for (int it = 0; it < 7; it++) {
            int idx = tid + it * 320;
            if (idx < 24*88) {
                int gh = row0 - 4 + r, gw = cl - 4;
                float v = 0.f;
                if (gh >= 0 && gh < HGT && gw >= 0 && gw < WID) v = xp[gh*WID + gw];
                tile[idx] = v;
            }
            r += 3; cl += 56;
            if (cl >= 88) { cl -= 88; r += 1; }
        }
    }
    __syncthreads();

    const int tx = tid % 20, ty = tid / 20;
    const int col0 = tx * 4;
    constexpr int PAD = KS / 2;
    constexpr int OFF = 4 - PAD;
    float a0 = 0.f, a1 = 0.f, a2 = 0.f, a3 = 0.f;
    float win[12];
    #pragma unroll
    for (int kh = 0; kh < KS; kh++) {
        int rb = (ty + 4 - PAD + kh)*88 + col0;
        float4 w0 = *(const float4*)&tile[rb];
        float4 w1 = *(const float4*)&tile[rb + 4];
        float4 w2 = *(const float4*)&tile[rb + 8];
        win[0]=w0.x; win[1]=w0.y; win[2]=w0.z;  win[3]=w0.w;
        win[4]=w1.x; win[5]=w1.y; win[6]=w1.z;  win[7]=w1.w;
        win[8]=w2.x; win[9]=w2.y; win[10]=w2.z; win[11]=w2.w;
        #pragma unroll
        for (int kw = 0; kw < KS; kw++) {
            float wv = wsm[kh*KS + kw];
            a0 += win[OFF + kw    ] * wv;
            a1 += win[OFF + kw + 1] * wv;
            a2 += win[OFF + kw + 2] * wv;
            a3 += win[OFF + kw + 3] * wv;
        }
    }
    int cb = (ty + 4)*88 + col0 + 4;
    float4 res = *(const float4*)&tile[cb];
    float* yp = g_y + (((size_t)br*NB + b)*CPB + c)*NPIX + (row0 + ty)*WID + col0;
    float4 r;
    r.x = fmaxf(a0 + bv + res.x, 0.f);
    r.y = fmaxf(a1 + bv + res.y, 0.f);
    r.z = fmaxf(a2 + bv + res.z, 0.f);
    r.w = fmaxf(a3 + bv + res.w, 0.f);
    *(float4*)yp = r;
}

__global__ void dwconv_all_kernel(const float* __restrict__ x,
                                  const float* __restrict__ w3, const float* __restrict__ b3,
                                  const float* __restrict__ w5, const float* __restrict__ b5,
                                  const float* __restrict__ w7, const float* __restrict__ b7,
                                  const float* __restrict__ w9, const float* __restrict__ b9,
                                  const float* __restrict__ wf,
                                  const float* __restrict__ wproj,
                                  const float* __restrict__ wqkv)
{
    __shared__ float tile[24*88];
    __shared__ float wsm[81];
    if (blockIdx.y == 256) {
        // prep slice: 5 blocks (z==0) x 320 threads cover all prep work
        if (blockIdx.z != 0) return;
        const int base = blockIdx.x * 320 + threadIdx.x;   // 0..1599
        for (int i = base; i < 65536; i += 1600) {
            g_wf32[i] = f2tf32(wf[i]);
            if (i < 32768) g_ctx[i] = 0.f;
            if (i < 4096)  g_wp32[i] = f2tf32(wproj[i]);
            if (i < 6144) {
                int j = i >> 5, cp = i & 31;
                uint32_t hi, lo;
                bf16_split_pair(wqkv[j*64 + 2*cp], wqkv[j*64 + 2*cp + 1], hi, lo);
                g_wq_hi[i] = hi;
                g_wq_lo[i] = lo;
            }
        }
        return;
    }
    const int br = blockIdx.y >> 6;
    const int c  = blockIdx.y & 63;
    switch (br) {
        case 0: dwconv_body<3>(x, w3, b3, 0, c, tile, wsm); break;
        case 1: dwconv_body<5>(x, w5, b5, 1, c, tile, wsm); break;
        case 2: dwconv_body<7>(x, w7, b7, 2, c, tile, wsm); break;
        default: dwconv_body<9>(x, w9, b9, 3, c, tile, wsm); break;
    }
}

// ---------------- K2: qkv via bf16 3-term MMA + softmax/ctx/stats (R11) --------
#define QSTR 194
#define WQSU 36
#define YSS  72
__global__ void qkv_kernel()
{
    extern __shared__ uint32_t smu[];
    uint32_t* wqh = smu;
    uint32_t* wql = smu + 192*WQSU;
    float*    ys  = (float*)(smu + 13824);
    const int tid  = threadIdx.x;
    const int brb  = blockIdx.y;
    const int tile = blockIdx.x;
    const int n0   = tile * 64;

    const float* yp = g_y + (size_t)brb * CPB * NPIX;
    for (int idx = tid; idx < 1536; idx += 256) {
        int j = idx >> 3, w4 = (idx & 7) * 4;
        uint4 vh = *(const uint4*)&g_wq_hi[j*32 + w4];
        uint4 vl = *(const uint4*)&g_wq_lo[j*32 + w4];
        *(uint4*)&wqh[j*WQSU + w4] = vh;
        *(uint4*)&wql[j*WQSU + w4] = vl;
    }
    for (int idx = tid; idx < 1024; idx += 256) {
        int c = idx >> 4, t4 = (idx & 15) * 4;
        float4 v = *(const float4*)&yp[(size_t)c*NPIX + n0 + t4];
        *(float4*)&ys[c*YSS + t4] = v;
    }
    __syncthreads();

    const int warp = tid >> 5, lane = tid & 31;
    const int wm = (warp >> 2) * 96;
    const int wn = (warp & 3) * 16;
    const int g = lane >> 2, t = lane & 3;

    float d[6][2][4];
    #pragma unroll
    for (int mf = 0; mf < 6; mf++)
        #pragma unroll
        for (int nf = 0; nf < 2; nf++)
            #pragma unroll
            for (int r = 0; r < 4; r++) d[mf][nf][r] = 0.f;

    #pragma unroll
    for (int ks = 0; ks < 4; ks++) {
        const int k0 = ks * 16;
        const int ci = ks * 8 + t;
        uint32_t bh[2][2], bl[2][2];
        #pragma unroll
        for (int nf = 0; nf < 2; nf++) {
            int ncol = wn + nf*8 + g;
            float f0 = ys[(k0 + 2*t    )*YSS + ncol];
            float f1 = ys[(k0 + 2*t + 1)*YSS + ncol];
            float f2 = ys[(k0 + 2*t + 8)*YSS + ncol];
            float f3 = ys[(k0 + 2*t + 9)*YSS + ncol];
            bf16_split_pair(f0, f1, bh[nf][0], bl[nf][0]);
            bf16_split_pair(f2, f3, bh[nf][1], bl[nf][1]);
        }
        #pragma unroll
        for (int mf = 0; mf < 6; mf++) {
            int r0 = wm + mf*16 + g;
            uint32_t ah0 = wqh[(r0    )*WQSU + ci];
            uint32_t ah1 = wqh[(r0 + 8)*WQSU + ci];
            uint32_t ah2 = wqh[(r0    )*WQSU + ci + 4];
            uint32_t ah3 = wqh[(r0 + 8)*WQSU + ci + 4];
            uint32_t al0 = wql[(r0    )*WQSU + ci];
            uint32_t al1 = wql[(r0 + 8)*WQSU + ci];
            uint32_t al2 = wql[(r0    )*WQSU + ci + 4];
            uint32_t al3 = wql[(r0 + 8)*WQSU + ci + 4];
            #pragma unroll
            for (int nf = 0; nf < 2; nf++) {
                mma_bf16(d[mf][nf], ah0, ah1, ah2, ah3, bl[nf][0], bl[nf][1]);
                mma_bf16(d[mf][nf], al0, al1, al2, al3, bh[nf][0], bh[nf][1]);
                mma_bf16(d[mf][nf], ah0, ah1, ah2, ah3, bh[nf][0], bh[nf][1]);
            }
        }
    }
    __syncthreads();

    float* qkvs = (float*)smu;  // [t=64][j stride QSTR]
    #pragma unroll
    for (int mf = 0; mf < 6; mf++) {
        int r0 = wm + mf*16 + g;
        #pragma unroll
        for (int nf = 0; nf < 2; nf++) {
            int c0 = wn + nf*8 + 2*t;
            qkvs[(c0    )*QSTR + r0    ] = d[mf][nf][0];
            qkvs[(c0 + 1)*QSTR + r0    ] = d[mf][nf][1];
            qkvs[(c0    )*QSTR + r0 + 8] = d[mf][nf][2];
            qkvs[(c0 + 1)*QSTR + r0 + 8] = d[mf][nf][3];
        }
    }
    __syncthreads();

    // k softmax over head-dim (8)
    for (int th = tid; th < 512; th += 256) {
        int tt = th & 63, h = th >> 6;
        float* kr = &qkvs[tt*QSTR + 64 + h*8];
        float kv[8];
        #pragma unroll
        for (int dd = 0; dd < 8; dd++) kv[dd] = kr[dd];
        float m = kv[0];
        #pragma unroll
        for (int dd = 1; dd < 8; dd++) m = fmaxf(m, kv[dd]);
        float e[8]; float s = 0.f;
        #pragma unroll
        for (int dd = 0; dd < 8; dd++) { e[dd] = __expf(kv[dd] - m); s += e[dd]; }
        float inv = 1.f / s;
        #pragma unroll
        for (int dd = 0; dd < 8; dd++) kr[dd] = e[dd] * inv;
    }
    __syncthreads();

    // per-tile q stats
    {
        int hd = tid >> 2, part = tid & 3;
        float vals[16];
        #pragma unroll
        for (int i = 0; i < 16; i++) vals[i] = qkvs[(part*16 + i)*QSTR + hd];
        float m = vals[0];
        #pragma unroll
        for (int i = 1; i < 16; i++) m = fmaxf(m, vals[i]);
        m = fmaxf(m, __shfl_xor_sync(0xffffffffu, m, 1));
        m = fmaxf(m, __shfl_xor_sync(0xffffffffu, m, 2));
        float s = 0.f;
        #pragma unroll
        for (int i = 0; i < 16; i++) s += __expf(vals[i] - m);
        s += __shfl_xor_sync(0xffffffffu, s, 1);
        s += __shfl_xor_sync(0xffffffffu, s, 2);
        if (part == 0) {
            size_t r = (size_t)brb*64 + hd;
            g_pm[r*NTILES + tile] = m;
            g_ps[r*NTILES + tile] = s;
        }
    }

    // partial ctx
    {
        int h  = tid >> 5;
        int dd = (tid >> 2) & 7;
        int ep = tid & 3;
        float ce0 = 0.f, ce1 = 0.f;
        #pragma unroll 4
        for (int tt = 0; tt < 64; tt++) {
            float  kv = qkvs[tt*QSTR + 64 + h*8 + dd];
            float2 vv = *(const float2*)&qkvs[tt*QSTR + 128 + h*8 + 2*ep];
            ce0 += kv * vv.x;
            ce1 += kv * vv.y;
        }
        float2 r = make_float2(ce0, ce1);
        *(float2*)&g_cpart[((size_t)tile*64 + brb)*512 + h*64 + dd*8 + 2*ep] = r;
    }

    // q scatter
    for (int idx = tid; idx < 1024; idx += 256) {
        int hd = idx >> 4, t4 = (idx & 15) * 4;
        float4 v;
        v.x = qkvs[(t4    )*QSTR + hd];
        v.y = qkvs[(t4 + 1)*QSTR + hd];
        v.z = qkvs[(t4 + 2)*QSTR + hd];
        v.w = qkvs[(t4 + 3)*QSTR + hd];
        *(float4*)&g_q[((size_t)brb*64 + hd)*NPIX + n0 + t4] = v;
    }
}

// ---------------- K3: merged ctx reduce + q stats combine ---------------------
__global__ void reduce_combine_kernel()
{
    const int tid = threadIdx.x;
    if (blockIdx.y < 10) {
        const int brb = blockIdx.x;
        const int t0  = blockIdx.y * 10;
        float s = 0.f;
        const float* p = g_cpart + (size_t)brb*512 + tid;
        #pragma unroll 5
        for (int t = 0; t < 10; t++)
            s += p[(size_t)(t0 + t)*64*512];
        atomicAdd(&g_ctx[(size_t)brb*512 + tid], s);
    } else {
        const int lane = tid & 31;
        const int q    = blockIdx.x + (blockIdx.y - 10) * 64;
        const int r    = q * 16 + (tid >> 5);
        const float* pm = g_pm + (size_t)r*NTILES;
        const float* ps = g_ps + (size_t)r*NTILES;

        float mv[4]; float m = -1e30f;
        #pragma unroll
        for (int j = 0; j < 4; j++) {
            int t = lane + 32*j;
            mv[j] = (t < NTILES) ? pm[t] : -1e30f;
            m = fmaxf(m, mv[j]);
        }
        #pragma unroll
        for (int off = 16; off; off >>= 1)
            m = fmaxf(m, __shfl_xor_sync(0xffffffffu, m, off));

        float s = 0.f;
        #pragma unroll
        for (int j = 0; j < 4; j++) {
            int t = lane + 32*j;
            if (t < NTILES) s += ps[t] * __expf(mv[j] - m);
        }
        #pragma unroll
        for (int off = 16; off; off >>= 1)
            s += __shfl_xor_sync(0xffffffffu, s, off);

        if (lane == 0) { g_qm[r] = m; g_qs[r] = s; }
    }
}

// ---------------- K5: softmax(q)@ctx, reshape, proj (tf32 MMA), scale (R11) ---
#define WPS 72
#define OSS 68
__global__ void attn_out_kernel(const float* __restrict__ bproj,
                                const float* __restrict__ scale)
{
    __shared__ uint32_t wp [64*WPS];
    __shared__ float out_s[32*OSS];
    __shared__ float p_s  [32*OSS];
    __shared__ float ctx_s[64];
    __shared__ float m_s[8];
    const int tid = threadIdx.x;
    const int brb = blockIdx.y;
    const int br  = brb >> 4;

    for (int idx = tid; idx < 4096; idx += 256) {
        int o = idx >> 6, f = idx & 63;
        wp[f*WPS + o] = g_wp32[idx];
    }
    const float scl = __ldg(&scale[br]);

    #pragma unroll
    for (int sub = 0; sub < 2; sub++) {
        const int gs = blockIdx.x * 64 + sub * 32;
        const int h  = gs / 800;

        __syncthreads();
        if (tid < 64) {
            int d = tid >> 3;
            float invS = 1.f / g_qs[(size_t)brb*64 + h*8 + d];
            ctx_s[tid] = g_ctx[((size_t)brb*NHEADS + h)*64 + tid] * invS;
        }
        if (tid >= 64 && tid < 72) m_s[tid - 64] = g_qm[(size_t)brb*64 + h*8 + (tid - 64)];
        __syncthreads();

        // Phase A
        {
            int g = tid >> 3, i = tid & 7;
            int np = gs + g;
            int n0 = (np % 800) * 8;
            const float* qp = g_q + ((size_t)brb*64 + h*8)*NPIX + n0 + i;
            float oo[8] = {0,0,0,0,0,0,0,0};
            #pragma unroll
            for (int d = 0; d < 8; d++) {
                float qv = __expf(qp[(size_t)d*NPIX] - m_s[d]);
                #pragma unroll
                for (int e = 0; e < 8; e++) oo[e] += qv * ctx_s[d*8 + e];
            }
            #pragma unroll
            for (int e = 0; e < 8; e++) out_s[g*OSS + i*8 + e] = oo[e];
        }
        __syncthreads();

        // Phase B via tf32 MMA
        {
            const int warp = tid >> 5, lane = tid & 31;
            const int pmB = (warp & 1) * 16;
            const int pnB = (warp >> 1) * 16;
            const int gq = lane >> 2, tq = lane & 3;
            float dD[2][4] = {{0,0,0,0},{0,0,0,0}};
            #pragma unroll
            for (int ks = 0; ks < 8; ks++) {
                int k0 = ks*8;
                uint32_t a0 = f2tf32(out_s[(pmB+gq  )*OSS + k0+tq  ]);
                uint32_t a1 = f2tf32(out_s[(pmB+gq+8)*OSS + k0+tq  ]);
                uint32_t a2 = f2tf32(out_s[(pmB+gq  )*OSS + k0+tq+4]);
                uint32_t a3 = f2tf32(out_s[(pmB+gq+8)*OSS + k0+tq+4]);
                #pragma unroll
                for (int nf = 0; nf < 2; nf++) {
                    int nc = pnB + nf*8 + gq;
                    uint32_t b0 = wp[(k0+tq  )*WPS + nc];
                    uint32_t b1 = wp[(k0+tq+4)*WPS + nc];
                    mma_tf32(dD[nf], a0, a1, a2, a3, b0, b1);
                }
            }
            #pragma unroll
            for (int nf = 0; nf < 2; nf++) {
                int c0 = pnB + nf*8 + 2*tq;
                float bp0 = bproj[c0], bp1 = bproj[c0+1];
                float2 lo, hi;
                lo.x = __uint_as_float(f2tf32((dD[nf][0] + bp0)*scl));
                lo.y = __uint_as_float(f2tf32((dD[nf][1] + bp1)*scl));
                hi.x = __uint_as_float(f2tf32((dD[nf][2] + bp0)*scl));
                hi.y = __uint_as_float(f2tf32((dD[nf][3] + bp1)*scl));
                *(float2*)&p_s[(pmB+gq  )*OSS + c0] = lo;
                *(float2*)&p_s[(pmB+gq+8)*OSS + c0] = hi;
            }
        }
        __syncthreads();

        float* ap = g_att + (size_t)brb*64*NPIX;
        for (int idx = tid; idx < 64*8; idx += 256) {
            int o = idx >> 3, seg = idx & 7;
            float4 r;
            r.x = p_s[(seg*4 + 0)*OSS + o];
            r.y = p_s[(seg*4 + 1)*OSS + o];
            r.z = p_s[(seg*4 + 2)*OSS + o];
            r.w = p_s[(seg*4 + 3)*OSS + o];
            *(float4*)&ap[(size_t)o*NPIX + gs + seg*4] = r;
        }
    }
}

// ---------------- K6: final 256x256 GEMM via mma.sync tf32 (R11) --------------
#define ASTR 36
#define BSTR 72
__global__ void final_kernel(const float* __restrict__ bf,
                             float* __restrict__ out)
{
    __shared__ uint32_t As[256*ASTR];
    __shared__ uint32_t Bs[32*BSTR];
    const int tid = threadIdx.x;
    const int n0  = blockIdx.x * 64;
    const int b   = blockIdx.y;

    const int warp = tid >> 5, lane = tid & 31;
    const int wo = (warp >> 1) * 64;
    const int wn = (warp & 1) * 32;
    const int g = lane >> 2, t = lane & 3;

    float d[4][4][4];
    #pragma unroll
    for (int mf = 0; mf < 4; mf++)
        #pragma unroll
        for (int nf = 0; nf < 4; nf++)
            #pragma unroll
            for (int r = 0; r < 4; r++) d[mf][nf][r] = 0.f;

    for (int kc = 0; kc < 256; kc += 32) {
        #pragma unroll
        for (int it = 0; it < 8; it++) {
            int idx = tid + it*256;
            int o = idx >> 3, k4 = (idx & 7) * 4;
            uint4 u = *(const uint4*)&g_wf32[o*256 + kc + k4];
            *(uint4*)&As[o*ASTR + k4] = u;
        }
        #pragma unroll
        for (int it = 0; it < 2; it++) {
            int idx = tid + it*256;
            int k = idx >> 4, n4 = (idx & 15) * 4;
            int kk = kc + k;
            uint4 u = *(const uint4*)&g_att[
                (((size_t)(kk >> 6)*NB + b)*64 + (kk & 63))*NPIX + n0 + n4];
            *(uint4*)&Bs[k*BSTR + n4] = u;
        }
        __syncthreads();

        #pragma unroll
        for (int kf = 0; kf < 4; kf++) {
            int k0 = kf*8;
            uint32_t a[4][4];
            #pragma unroll
            for (int mf = 0; mf < 4; mf++) {
                int orow = wo + mf*16 + g;
                a[mf][0] = As[(orow    )*ASTR + k0 + t];
                a[mf][1] = As[(orow + 8)*ASTR + k0 + t];
                a[mf][2] = As[(orow    )*ASTR + k0 + t + 4];
                a[mf][3] = As[(orow + 8)*ASTR + k0 + t + 4];
            }
            uint32_t bb[4][2];
            #pragma unroll
            for (int nf = 0; nf < 4; nf++) {
                int ncol = wn + nf*8 + g;
                bb[nf][0] = Bs[(k0 + t    )*BSTR + ncol];
                bb[nf][1] = Bs[(k0 + t + 4)*BSTR + ncol];
            }
            #pragma unroll
            for (int mf = 0; mf < 4; mf++)
                #pragma unroll
                for (int nf = 0; nf < 4; nf++)
                    mma_tf32(d[mf][nf], a[mf][0], a[mf][1], a[mf][2], a[mf][3],
                             bb[nf][0], bb[nf][1]);
        }
        __syncthreads();
    }

    #pragma unroll
    for (int mf = 0; mf < 4; mf++) {
        int o_lo = wo + mf*16 + g;
        int o_hi = o_lo + 8;
        float bf_lo = __ldg(&bf[o_lo]);
        float bf_hi = __ldg(&bf[o_hi]);
        float* base_lo = &out[((size_t)b*256 + o_lo)*NPIX + n0 + wn];
        float* base_hi = &out[((size_t)b*256 + o_hi)*NPIX + n0 + wn];
        #pragma unroll
        for (int nf = 0; nf < 4; nf++) {
            int nc = nf*8 + 2*t;
            float2 r0 = make_float2(d[mf][nf][0] + bf_lo, d[mf][nf][1] + bf_lo);
            float2 r1 = make_float2(d[mf][nf][2] + bf_hi, d[mf][nf][3] + bf_hi);
            *(float2*)&base_lo[nc] = r0;
            *(float2*)&base_hi[nc] = r1;
        }
    }
}

// ---------------- launch ---------------------------------------------------------
extern "C" void kernel_launch(void* const* d_in, const int* in_sizes, int n_in,
                              void* d_out, int out_size)
{
    const float* x     = (const float*)d_in[0];
    const float* w3    = (const float*)d_in[1];
    const float* b3    = (const float*)d_in[2];
    const float* w5    = (const float*)d_in[3];
    const float* b5    = (const float*)d_in[4];
    const float* w7    = (const float*)d_in[5];
    const float* b7    = (const float*)d_in[6];
    const float* w9    = (const float*)d_in[7];
    const float* b9    = (const float*)d_in[8];
    const float* wqkv  = (const float*)d_in[9];
    const float* wproj = (const float*)d_in[10];
    const float* bproj = (const float*)d_in[11];
    const float* wf    = (const float*)d_in[12];
    const float* bf    = (const float*)d_in[13];
    const float* scale = (const float*)d_in[14];
    float* out = (float*)d_out;

    dwconv_all_kernel<<<dim3(5, 257, 16), 320>>>(x, w3, b3, w5, b5, w7, b7, w9, b9,
                                                 wf, wproj, wqkv);

    static bool attr_set = false;
    if (!attr_set) {
        cudaFuncSetAttribute(qkv_kernel,
                             cudaFuncAttributeMaxDynamicSharedMemorySize, 73728);
        attr_set = true;
    }
    qkv_kernel<<<dim3(100, 64), 256, 73728>>>();
    reduce_combine_kernel<<<dim3(64, 14), 512>>>();
    attn_out_kernel<<<dim3(100, 64), 256>>>(bproj, scale);
    final_kernel<<<dim3(100, 16), 256>>>(bf, out);
}